// round 1
// baseline (speedup 1.0000x reference)
#include <cuda_runtime.h>
#include <cstdint>

#define B_DIM 4
#define T_DIM 4096
#define C_DIM 2048
#define H_DIM 128

// Scratch for projected q, k, v: [B, T, H] fp32 each (8 MB each).
__device__ float g_q[(size_t)B_DIM * T_DIM * H_DIM];
__device__ float g_k[(size_t)B_DIM * T_DIM * H_DIM];
__device__ float g_v[(size_t)B_DIM * T_DIM * H_DIM];

__device__ __forceinline__ uint32_t f2tf32(float f) {
    uint32_t r;
    asm("cvt.rna.tf32.f32 %0, %1;" : "=r"(r) : "f"(f));
    return r;
}

// D = A(16x8, row) * B(8x8, col) + D, tf32 inputs, fp32 accum.
__device__ __forceinline__ void mma_tf32(float* c, const uint32_t* a, const uint32_t* b) {
    asm volatile(
        "mma.sync.aligned.m16n8k8.row.col.f32.tf32.tf32.f32 "
        "{%0,%1,%2,%3}, {%4,%5,%6,%7}, {%8,%9}, {%0,%1,%2,%3};\n"
        : "+f"(c[0]), "+f"(c[1]), "+f"(c[2]), "+f"(c[3])
        : "r"(a[0]), "r"(a[1]), "r"(a[2]), "r"(a[3]), "r"(b[0]), "r"(b[1]));
}

// ============================================================================
// Kernel 1: projections. out[m, h] = sum_c idx[m, c] * W[h, c]
// Block tile: 128 (M) x 128 (N=H), K-chunk 16. 256 threads = 8 warps,
// warp tile 32x64. blockIdx.y selects Wq/Wk/Wv.
// ============================================================================
__global__ void __launch_bounds__(256, 2) proj_kernel(
    const float* __restrict__ idx,
    const float* __restrict__ Wq,
    const float* __restrict__ Wk,
    const float* __restrict__ Wv)
{
    // stride 20 words: (g*20 + t4) % 32 is conflict-free for fragment loads
    __shared__ uint32_t sA[128 * 20];
    __shared__ uint32_t sB[128 * 20];

    const int tid  = threadIdx.x;
    const int warp = tid >> 5, lane = tid & 31;
    const int g = lane >> 2, t4 = lane & 3;
    const int mo = (warp & 3) * 32;   // warp M offset within block tile
    const int no = (warp >> 2) * 64;  // warp N offset
    const int row0 = blockIdx.x * 128;

    const float* W = (blockIdx.y == 0) ? Wq : (blockIdx.y == 1 ? Wk : Wv);
    float* out = (blockIdx.y == 0) ? g_q : (blockIdx.y == 1 ? g_k : g_v);

    float acc[2][8][4];
#pragma unroll
    for (int i = 0; i < 2; i++)
#pragma unroll
        for (int j = 0; j < 8; j++)
#pragma unroll
            for (int l = 0; l < 4; l++) acc[i][j][l] = 0.f;

    const int lr = tid >> 2;        // 0..63 (load row)
    const int lc = (tid & 3) * 4;   // 0,4,8,12 (load col)

    for (int kb = 0; kb < C_DIM; kb += 16) {
#pragma unroll
        for (int rr = 0; rr < 2; rr++) {
            int r = lr + rr * 64;
            float4 fa = *reinterpret_cast<const float4*>(idx + (size_t)(row0 + r) * C_DIM + kb + lc);
            float4 fb = *reinterpret_cast<const float4*>(W + (size_t)r * C_DIM + kb + lc);
            sA[r * 20 + lc + 0] = f2tf32(fa.x);
            sA[r * 20 + lc + 1] = f2tf32(fa.y);
            sA[r * 20 + lc + 2] = f2tf32(fa.z);
            sA[r * 20 + lc + 3] = f2tf32(fa.w);
            sB[r * 20 + lc + 0] = f2tf32(fb.x);
            sB[r * 20 + lc + 1] = f2tf32(fb.y);
            sB[r * 20 + lc + 2] = f2tf32(fb.z);
            sB[r * 20 + lc + 3] = f2tf32(fb.w);
        }
        __syncthreads();

#pragma unroll
        for (int ks = 0; ks < 2; ks++) {
            const int kk = ks * 8;
            uint32_t af[2][4];
#pragma unroll
            for (int mt = 0; mt < 2; mt++) {
                int mr = mo + mt * 16;
                af[mt][0] = sA[(mr + g) * 20 + kk + t4];
                af[mt][1] = sA[(mr + g + 8) * 20 + kk + t4];
                af[mt][2] = sA[(mr + g) * 20 + kk + t4 + 4];
                af[mt][3] = sA[(mr + g + 8) * 20 + kk + t4 + 4];
            }
#pragma unroll
            for (int nt = 0; nt < 8; nt++) {
                uint32_t bf[2];
                int nc = no + nt * 8 + g;
                bf[0] = sB[nc * 20 + kk + t4];
                bf[1] = sB[nc * 20 + kk + t4 + 4];
                mma_tf32(acc[0][nt], af[0], bf);
                mma_tf32(acc[1][nt], af[1], bf);
            }
        }
        __syncthreads();
    }

#pragma unroll
    for (int mt = 0; mt < 2; mt++) {
#pragma unroll
        for (int nt = 0; nt < 8; nt++) {
            int r  = row0 + mo + mt * 16 + g;
            int cc = no + nt * 8 + 2 * t4;
            out[(size_t)r * H_DIM + cc]           = acc[mt][nt][0];
            out[(size_t)r * H_DIM + cc + 1]       = acc[mt][nt][1];
            out[(size_t)(r + 8) * H_DIM + cc]     = acc[mt][nt][2];
            out[(size_t)(r + 8) * H_DIM + cc + 1] = acc[mt][nt][3];
        }
    }
}

// ============================================================================
// Kernel 2: flash attention.
//   S[i, j] = scale * k_i . q_j   (note: rows are K, columns are Q per ref)
//   causal mask j <= i, softmax over j (online), O = P . V
// Block: 64 rows (i) per block, iterate j-tiles of 64. 256 threads, 8 warps.
// S tile: warp (w&3) does 16 M-rows, (w>>2) does 32 of 64 S-cols.
// O tile: warp (w&3) does 16 M-rows, (w>>2) does 64 of 128 H-cols.
// ============================================================================
#define SK_STRIDE 132  // K/Q tiles: row-indexed frag loads conflict-free
#define SV_STRIDE 136  // V tile: k-row-indexed frag loads conflict-free
#define SS_STRIDE 68   // S/P tile

#define SMEM_WORDS (64 * SK_STRIDE * 2 + 64 * SV_STRIDE + 64 * SS_STRIDE + 3 * 64)
#define SMEM_BYTES (SMEM_WORDS * 4)

__global__ void __launch_bounds__(256, 1) attn_kernel(float* __restrict__ out)
{
    extern __shared__ uint32_t smbuf[];
    uint32_t* sK = smbuf;
    uint32_t* sQ = sK + 64 * SK_STRIDE;
    uint32_t* sV = sQ + 64 * SK_STRIDE;
    uint32_t* sS = sV + 64 * SV_STRIDE;
    float* sM  = (float*)(sS + 64 * SS_STRIDE);
    float* sL  = sM + 64;
    float* sAl = sL + 64;

    const int tid  = threadIdx.x;
    const int warp = tid >> 5, lane = tid & 31;
    const int g = lane >> 2, t4 = lane & 3;
    const int i0 = blockIdx.x * 64;
    const int b  = blockIdx.y;
    const float scale = 0.022097086912079608f;  // 2048^-0.5
    const float NEG_INF = -__int_as_float(0x7f800000);

    // Load K tile (rows i0..i0+63) once, converted to tf32.
    {
        const float* kb = g_k + ((size_t)b * T_DIM + i0) * H_DIM;
#pragma unroll
        for (int i = 0; i < 8; i++) {
            int idx4 = tid + i * 256;
            int r = idx4 >> 5;
            int c = (idx4 & 31) * 4;
            float4 f = *reinterpret_cast<const float4*>(kb + (size_t)r * H_DIM + c);
            sK[r * SK_STRIDE + c + 0] = f2tf32(f.x);
            sK[r * SK_STRIDE + c + 1] = f2tf32(f.y);
            sK[r * SK_STRIDE + c + 2] = f2tf32(f.z);
            sK[r * SK_STRIDE + c + 3] = f2tf32(f.w);
        }
    }
    if (tid < 64) { sM[tid] = NEG_INF; sL[tid] = 0.f; }

    const int mo = (warp & 3) * 16;   // M-row offset (both S and O)
    const int so = (warp >> 2) * 32;  // S col offset
    const int ho = (warp >> 2) * 64;  // O col offset

    float o[8][4];
#pragma unroll
    for (int nt = 0; nt < 8; nt++)
#pragma unroll
        for (int l = 0; l < 4; l++) o[nt][l] = 0.f;

    const int rrow = tid >> 2;  // softmax row 0..63
    const int q4   = tid & 3;   // quad lane within row

    for (int j0 = 0; j0 <= i0; j0 += 64) {
        // Load Q, V tiles for this j-tile.
        const float* qb = g_q + ((size_t)b * T_DIM + j0) * H_DIM;
        const float* vb = g_v + ((size_t)b * T_DIM + j0) * H_DIM;
#pragma unroll
        for (int i = 0; i < 8; i++) {
            int idx4 = tid + i * 256;
            int r = idx4 >> 5;
            int c = (idx4 & 31) * 4;
            float4 fq = *reinterpret_cast<const float4*>(qb + (size_t)r * H_DIM + c);
            float4 fv = *reinterpret_cast<const float4*>(vb + (size_t)r * H_DIM + c);
            sQ[r * SK_STRIDE + c + 0] = f2tf32(fq.x);
            sQ[r * SK_STRIDE + c + 1] = f2tf32(fq.y);
            sQ[r * SK_STRIDE + c + 2] = f2tf32(fq.z);
            sQ[r * SK_STRIDE + c + 3] = f2tf32(fq.w);
            sV[r * SV_STRIDE + c + 0] = f2tf32(fv.x);
            sV[r * SV_STRIDE + c + 1] = f2tf32(fv.y);
            sV[r * SV_STRIDE + c + 2] = f2tf32(fv.z);
            sV[r * SV_STRIDE + c + 3] = f2tf32(fv.w);
        }
        __syncthreads();

        // S = K . Q^T over H=128 (16 k-steps)
        float s[4][4];
#pragma unroll
        for (int nt = 0; nt < 4; nt++)
#pragma unroll
            for (int l = 0; l < 4; l++) s[nt][l] = 0.f;

#pragma unroll
        for (int ks = 0; ks < 16; ks++) {
            const int kk = ks * 8;
            uint32_t af[4];
            af[0] = sK[(mo + g) * SK_STRIDE + kk + t4];
            af[1] = sK[(mo + g + 8) * SK_STRIDE + kk + t4];
            af[2] = sK[(mo + g) * SK_STRIDE + kk + t4 + 4];
            af[3] = sK[(mo + g + 8) * SK_STRIDE + kk + t4 + 4];
#pragma unroll
            for (int nt = 0; nt < 4; nt++) {
                uint32_t bf[2];
                int nc = so + nt * 8 + g;
                bf[0] = sQ[nc * SK_STRIDE + kk + t4];
                bf[1] = sQ[nc * SK_STRIDE + kk + t4 + 4];
                mma_tf32(s[nt], af, bf);
            }
        }
        // Scale and park S in shared (fp32 bits).
#pragma unroll
        for (int nt = 0; nt < 4; nt++) {
            int cc = so + nt * 8 + 2 * t4;
            sS[(mo + g) * SS_STRIDE + cc]         = __float_as_uint(s[nt][0] * scale);
            sS[(mo + g) * SS_STRIDE + cc + 1]     = __float_as_uint(s[nt][1] * scale);
            sS[(mo + g + 8) * SS_STRIDE + cc]     = __float_as_uint(s[nt][2] * scale);
            sS[(mo + g + 8) * SS_STRIDE + cc + 1] = __float_as_uint(s[nt][3] * scale);
        }
        __syncthreads();

        // Online softmax: 4 threads per row, 16 cols each.
        {
            float sv[16];
            float mloc = NEG_INF;
            const int gi = i0 + rrow;
#pragma unroll
            for (int t = 0; t < 16; t++) {
                int c = q4 + t * 4;
                float val = __uint_as_float(sS[rrow * SS_STRIDE + c]);
                bool valid = (j0 + c) <= gi;
                sv[t] = valid ? val : NEG_INF;
                mloc = fmaxf(mloc, sv[t]);
            }
            mloc = fmaxf(mloc, __shfl_xor_sync(0xffffffffu, mloc, 1));
            mloc = fmaxf(mloc, __shfl_xor_sync(0xffffffffu, mloc, 2));
            float mprev = sM[rrow];
            float mnew  = fmaxf(mprev, mloc);
            float alpha = __expf(mprev - mnew);  // 0 on first tile (mprev=-inf)
            float lsum = 0.f;
#pragma unroll
            for (int t = 0; t < 16; t++) {
                int c = q4 + t * 4;
                float p = __expf(sv[t] - mnew);  // masked -> exp(-inf) = 0
                lsum += p;
                sS[rrow * SS_STRIDE + c] = f2tf32(p);  // P stored as tf32 bits
            }
            lsum += __shfl_xor_sync(0xffffffffu, lsum, 1);
            lsum += __shfl_xor_sync(0xffffffffu, lsum, 2);
            if (q4 == 0) {
                sL[rrow] = sL[rrow] * alpha + lsum;
                sM[rrow] = mnew;
                sAl[rrow] = alpha;
            }
        }
        __syncthreads();

        // Rescale O accumulators by alpha.
        {
            float a0 = sAl[mo + g], a1 = sAl[mo + g + 8];
#pragma unroll
            for (int nt = 0; nt < 8; nt++) {
                o[nt][0] *= a0; o[nt][1] *= a0;
                o[nt][2] *= a1; o[nt][3] *= a1;
            }
        }

        // O += P . V over 64 (8 k-steps)
#pragma unroll
        for (int ks = 0; ks < 8; ks++) {
            const int kk = ks * 8;
            uint32_t af[4];
            af[0] = sS[(mo + g) * SS_STRIDE + kk + t4];
            af[1] = sS[(mo + g + 8) * SS_STRIDE + kk + t4];
            af[2] = sS[(mo + g) * SS_STRIDE + kk + t4 + 4];
            af[3] = sS[(mo + g + 8) * SS_STRIDE + kk + t4 + 4];
#pragma unroll
            for (int nt = 0; nt < 8; nt++) {
                uint32_t bf[2];
                int hc = ho + nt * 8 + g;
                bf[0] = sV[(kk + t4) * SV_STRIDE + hc];
                bf[1] = sV[(kk + t4 + 4) * SV_STRIDE + hc];
                mma_tf32(o[nt], af, bf);
            }
        }
        __syncthreads();
    }

    // Epilogue: normalize by l and store.
    const float il0 = 1.f / sL[mo + g];
    const float il1 = 1.f / sL[mo + g + 8];
    float* ob = out + ((size_t)b * T_DIM + i0 + mo) * H_DIM;
#pragma unroll
    for (int nt = 0; nt < 8; nt++) {
        int cc = ho + nt * 8 + 2 * t4;
        ob[(size_t)g * H_DIM + cc]           = o[nt][0] * il0;
        ob[(size_t)g * H_DIM + cc + 1]       = o[nt][1] * il0;
        ob[(size_t)(g + 8) * H_DIM + cc]     = o[nt][2] * il1;
        ob[(size_t)(g + 8) * H_DIM + cc + 1] = o[nt][3] * il1;
    }
}

extern "C" void kernel_launch(void* const* d_in, const int* in_sizes, int n_in,
                              void* d_out, int out_size)
{
    const float* idx = (const float*)d_in[0];
    const float* Wq  = (const float*)d_in[1];
    const float* Wk  = (const float*)d_in[2];
    const float* Wv  = (const float*)d_in[3];
    float* out = (float*)d_out;

    (void)in_sizes; (void)n_in; (void)out_size;

    cudaFuncSetAttribute(attn_kernel, cudaFuncAttributeMaxDynamicSharedMemorySize, SMEM_BYTES);

    proj_kernel<<<dim3((B_DIM * T_DIM) / 128, 3), 256>>>(idx, Wq, Wk, Wv);
    attn_kernel<<<dim3(T_DIM / 64, B_DIM), 256, SMEM_BYTES>>>(out);
}

// round 2
// speedup vs baseline: 1.0693x; 1.0693x over previous
#include <cuda_runtime.h>
#include <cstdint>

#define B_DIM 4
#define T_DIM 4096
#define C_DIM 2048
#define H_DIM 128

// Scratch for projected q, k, v: [B, T, H] fp32 each (8 MB each).
__device__ float g_q[(size_t)B_DIM * T_DIM * H_DIM];
__device__ float g_k[(size_t)B_DIM * T_DIM * H_DIM];
__device__ float g_v[(size_t)B_DIM * T_DIM * H_DIM];

__device__ __forceinline__ uint32_t f2tf32(float f) {
    uint32_t r;
    asm("cvt.rna.tf32.f32 %0, %1;" : "=r"(r) : "f"(f));
    return r;
}

// D = A(16x8, row) * B(8x8, col) + D, tf32 inputs, fp32 accum.
__device__ __forceinline__ void mma_tf32(float* c, const uint32_t* a, const uint32_t* b) {
    asm volatile(
        "mma.sync.aligned.m16n8k8.row.col.f32.tf32.tf32.f32 "
        "{%0,%1,%2,%3}, {%4,%5,%6,%7}, {%8,%9}, {%0,%1,%2,%3};\n"
        : "+f"(c[0]), "+f"(c[1]), "+f"(c[2]), "+f"(c[3])
        : "r"(a[0]), "r"(a[1]), "r"(a[2]), "r"(a[3]), "r"(b[0]), "r"(b[1]));
}

// ============================================================================
// Kernel 1: projections. out[m, h] = sum_c idx[m, c] * W[h, c]
// Block tile 128(M) x 128(N=H), K-chunk 32, smem double-buffered:
//   iter: LDG next chunk -> regs | MMA current buffer | cvt+STS next buffer
// grid = (3, M/128): the 3 sibling blocks (q/k/v of same rows) are adjacent
// bids -> concurrent -> idx rows hit L2.
// ============================================================================
#define PSTR 36  // 32 + 4 pad: conflict-free fragment loads

__global__ void __launch_bounds__(256) proj_kernel(
    const float* __restrict__ idx,
    const float* __restrict__ Wq,
    const float* __restrict__ Wk,
    const float* __restrict__ Wv)
{
    __shared__ uint32_t sA[2][128 * PSTR];
    __shared__ uint32_t sB[2][128 * PSTR];

    const int tid  = threadIdx.x;
    const int warp = tid >> 5, lane = tid & 31;
    const int g = lane >> 2, t4 = lane & 3;
    const int mo = (warp & 3) * 32;   // warp M offset
    const int no = (warp >> 2) * 64;  // warp N offset
    const int row0 = blockIdx.y * 128;
    const int wsel = blockIdx.x;

    const float* W = (wsel == 0) ? Wq : (wsel == 1 ? Wk : Wv);
    float* out = (wsel == 0) ? g_q : (wsel == 1 ? g_k : g_v);

    float acc[2][8][4];
#pragma unroll
    for (int i = 0; i < 2; i++)
#pragma unroll
        for (int j = 0; j < 8; j++)
#pragma unroll
            for (int l = 0; l < 4; l++) acc[i][j][l] = 0.f;

    // load map: 2 threads per row, 16 floats each
    const int lr = tid >> 1;
    const int lc = (tid & 1) * 16;
    const float* aptr = idx + (size_t)(row0 + lr) * C_DIM + lc;
    const float* bptr = W + (size_t)lr * C_DIM + lc;

    float4 pa[4], pb[4];

    // prologue: chunk 0
#pragma unroll
    for (int j = 0; j < 4; j++) {
        pa[j] = *reinterpret_cast<const float4*>(aptr + j * 4);
        pb[j] = *reinterpret_cast<const float4*>(bptr + j * 4);
    }
#pragma unroll
    for (int j = 0; j < 4; j++) {
        uint4 ua = { f2tf32(pa[j].x), f2tf32(pa[j].y), f2tf32(pa[j].z), f2tf32(pa[j].w) };
        uint4 ub = { f2tf32(pb[j].x), f2tf32(pb[j].y), f2tf32(pb[j].z), f2tf32(pb[j].w) };
        *reinterpret_cast<uint4*>(&sA[0][lr * PSTR + lc + j * 4]) = ua;
        *reinterpret_cast<uint4*>(&sB[0][lr * PSTR + lc + j * 4]) = ub;
    }
    __syncthreads();

    int cur = 0;
    for (int kb = 0; kb < C_DIM; kb += 32) {
        const bool more = (kb + 32) < C_DIM;
        if (more) {
#pragma unroll
            for (int j = 0; j < 4; j++) {
                pa[j] = *reinterpret_cast<const float4*>(aptr + kb + 32 + j * 4);
                pb[j] = *reinterpret_cast<const float4*>(bptr + kb + 32 + j * 4);
            }
        }

        const uint32_t* bufA = sA[cur];
        const uint32_t* bufB = sB[cur];
#pragma unroll
        for (int ks = 0; ks < 4; ks++) {
            const int kk = ks * 8;
            uint32_t af[2][4];
#pragma unroll
            for (int mt = 0; mt < 2; mt++) {
                int mr = mo + mt * 16;
                af[mt][0] = bufA[(mr + g) * PSTR + kk + t4];
                af[mt][1] = bufA[(mr + g + 8) * PSTR + kk + t4];
                af[mt][2] = bufA[(mr + g) * PSTR + kk + t4 + 4];
                af[mt][3] = bufA[(mr + g + 8) * PSTR + kk + t4 + 4];
            }
#pragma unroll
            for (int nt = 0; nt < 8; nt++) {
                uint32_t bf[2];
                int nc = no + nt * 8 + g;
                bf[0] = bufB[nc * PSTR + kk + t4];
                bf[1] = bufB[nc * PSTR + kk + t4 + 4];
                mma_tf32(acc[0][nt], af[0], bf);
                mma_tf32(acc[1][nt], af[1], bf);
            }
        }

        if (more) {
#pragma unroll
            for (int j = 0; j < 4; j++) {
                uint4 ua = { f2tf32(pa[j].x), f2tf32(pa[j].y), f2tf32(pa[j].z), f2tf32(pa[j].w) };
                uint4 ub = { f2tf32(pb[j].x), f2tf32(pb[j].y), f2tf32(pb[j].z), f2tf32(pb[j].w) };
                *reinterpret_cast<uint4*>(&sA[cur ^ 1][lr * PSTR + lc + j * 4]) = ua;
                *reinterpret_cast<uint4*>(&sB[cur ^ 1][lr * PSTR + lc + j * 4]) = ub;
            }
        }
        __syncthreads();
        cur ^= 1;
    }

#pragma unroll
    for (int mt = 0; mt < 2; mt++) {
#pragma unroll
        for (int nt = 0; nt < 8; nt++) {
            int r  = row0 + mo + mt * 16 + g;
            int cc = no + nt * 8 + 2 * t4;
            out[(size_t)r * H_DIM + cc]           = acc[mt][nt][0];
            out[(size_t)r * H_DIM + cc + 1]       = acc[mt][nt][1];
            out[(size_t)(r + 8) * H_DIM + cc]     = acc[mt][nt][2];
            out[(size_t)(r + 8) * H_DIM + cc + 1] = acc[mt][nt][3];
        }
    }
}

// ============================================================================
// Kernel 2: flash attention.
//   S[i, j] = scale * k_i . q_j   (rows = K, cols = Q per the reference)
//   causal j <= i, online softmax over j, O = P . V
// BM=64 rows(i) per block, BN=128 (j) per iteration. 256 threads, 8 warps.
// Blocks launched heavy-first (reversed i0) for load balance.
// ============================================================================
#define SK_STRIDE 132  // K/Q: row-major frag loads conflict-free
#define SV_STRIDE 136  // V: k-row-indexed frag loads conflict-free
#define SS_STRIDE 132  // S/P tile 64 x 128

#define SMEM_WORDS (64 * SK_STRIDE + 128 * SK_STRIDE + 128 * SV_STRIDE + 64 * SS_STRIDE + 3 * 64)
#define SMEM_BYTES (SMEM_WORDS * 4)

__global__ void __launch_bounds__(256, 1) attn_kernel(float* __restrict__ out)
{
    extern __shared__ uint32_t smbuf[];
    uint32_t* sK = smbuf;                       // 64 x SK_STRIDE
    uint32_t* sQ = sK + 64 * SK_STRIDE;         // 128 x SK_STRIDE
    uint32_t* sV = sQ + 128 * SK_STRIDE;        // 128 x SV_STRIDE
    uint32_t* sS = sV + 128 * SV_STRIDE;        // 64 x SS_STRIDE
    float* sM  = (float*)(sS + 64 * SS_STRIDE);
    float* sL  = sM + 64;
    float* sAl = sL + 64;

    const int tid  = threadIdx.x;
    const int warp = tid >> 5, lane = tid & 31;
    const int g = lane >> 2, t4 = lane & 3;
    const int i0 = (gridDim.x - 1 - blockIdx.x) * 64;  // heavy blocks first
    const int b  = blockIdx.y;
    const float scale = 0.022097086912079608f;  // 2048^-0.5
    const float NEG_INF = -__int_as_float(0x7f800000);

    // Load K tile (rows i0..i0+63), tf32.
    {
        const float* kb = g_k + ((size_t)b * T_DIM + i0) * H_DIM;
#pragma unroll 4
        for (int i = 0; i < 8; i++) {
            int idx4 = tid + i * 256;
            int r = idx4 >> 5;
            int c = (idx4 & 31) * 4;
            float4 f = *reinterpret_cast<const float4*>(kb + (size_t)r * H_DIM + c);
            sK[r * SK_STRIDE + c + 0] = f2tf32(f.x);
            sK[r * SK_STRIDE + c + 1] = f2tf32(f.y);
            sK[r * SK_STRIDE + c + 2] = f2tf32(f.z);
            sK[r * SK_STRIDE + c + 3] = f2tf32(f.w);
        }
    }
    if (tid < 64) { sM[tid] = NEG_INF; sL[tid] = 0.f; }

    const int mo = (warp & 3) * 16;   // M-row offset (S and O)
    const int so = (warp >> 2) * 64;  // S col offset (of 128)
    const int ho = (warp >> 2) * 64;  // O col offset (of 128)

    float o[8][4];
#pragma unroll
    for (int nt = 0; nt < 8; nt++)
#pragma unroll
        for (int l = 0; l < 4; l++) o[nt][l] = 0.f;

    const int rrow = tid >> 2;  // softmax row 0..63
    const int q4   = tid & 3;

    for (int j0 = 0; j0 <= i0; j0 += 128) {
        // Load Q, V tiles (128 rows each) for this j-tile.
        const float* qb = g_q + ((size_t)b * T_DIM + j0) * H_DIM;
        const float* vb = g_v + ((size_t)b * T_DIM + j0) * H_DIM;
#pragma unroll 4
        for (int i = 0; i < 16; i++) {
            int idx4 = tid + i * 256;
            int r = idx4 >> 5;
            int c = (idx4 & 31) * 4;
            float4 fq = *reinterpret_cast<const float4*>(qb + (size_t)r * H_DIM + c);
            float4 fv = *reinterpret_cast<const float4*>(vb + (size_t)r * H_DIM + c);
            sQ[r * SK_STRIDE + c + 0] = f2tf32(fq.x);
            sQ[r * SK_STRIDE + c + 1] = f2tf32(fq.y);
            sQ[r * SK_STRIDE + c + 2] = f2tf32(fq.z);
            sQ[r * SK_STRIDE + c + 3] = f2tf32(fq.w);
            sV[r * SV_STRIDE + c + 0] = f2tf32(fv.x);
            sV[r * SV_STRIDE + c + 1] = f2tf32(fv.y);
            sV[r * SV_STRIDE + c + 2] = f2tf32(fv.z);
            sV[r * SV_STRIDE + c + 3] = f2tf32(fv.w);
        }
        __syncthreads();

        // S = K . Q^T over H=128 (16 k-steps), S tile 64 x 128
        float s[8][4];
#pragma unroll
        for (int nt = 0; nt < 8; nt++)
#pragma unroll
            for (int l = 0; l < 4; l++) s[nt][l] = 0.f;

#pragma unroll
        for (int ks = 0; ks < 16; ks++) {
            const int kk = ks * 8;
            uint32_t af[4];
            af[0] = sK[(mo + g) * SK_STRIDE + kk + t4];
            af[1] = sK[(mo + g + 8) * SK_STRIDE + kk + t4];
            af[2] = sK[(mo + g) * SK_STRIDE + kk + t4 + 4];
            af[3] = sK[(mo + g + 8) * SK_STRIDE + kk + t4 + 4];
#pragma unroll
            for (int nt = 0; nt < 8; nt++) {
                uint32_t bf[2];
                int nc = so + nt * 8 + g;
                bf[0] = sQ[nc * SK_STRIDE + kk + t4];
                bf[1] = sQ[nc * SK_STRIDE + kk + t4 + 4];
                mma_tf32(s[nt], af, bf);
            }
        }
        // Scale and park S in shared (fp32 bits).
#pragma unroll
        for (int nt = 0; nt < 8; nt++) {
            int cc = so + nt * 8 + 2 * t4;
            sS[(mo + g) * SS_STRIDE + cc]         = __float_as_uint(s[nt][0] * scale);
            sS[(mo + g) * SS_STRIDE + cc + 1]     = __float_as_uint(s[nt][1] * scale);
            sS[(mo + g + 8) * SS_STRIDE + cc]     = __float_as_uint(s[nt][2] * scale);
            sS[(mo + g + 8) * SS_STRIDE + cc + 1] = __float_as_uint(s[nt][3] * scale);
        }
        __syncthreads();

        // Online softmax: 4 threads per row, 32 cols each.
        {
            float sv[32];
            float mloc = NEG_INF;
            const int gi = i0 + rrow;
#pragma unroll
            for (int t = 0; t < 32; t++) {
                int c = q4 + t * 4;
                float val = __uint_as_float(sS[rrow * SS_STRIDE + c]);
                bool valid = (j0 + c) <= gi;
                sv[t] = valid ? val : NEG_INF;
                mloc = fmaxf(mloc, sv[t]);
            }
            mloc = fmaxf(mloc, __shfl_xor_sync(0xffffffffu, mloc, 1));
            mloc = fmaxf(mloc, __shfl_xor_sync(0xffffffffu, mloc, 2));
            float mprev = sM[rrow];
            float mnew  = fmaxf(mprev, mloc);
            float alpha = __expf(mprev - mnew);
            float lsum = 0.f;
#pragma unroll
            for (int t = 0; t < 32; t++) {
                int c = q4 + t * 4;
                float p = __expf(sv[t] - mnew);
                lsum += p;
                sS[rrow * SS_STRIDE + c] = f2tf32(p);  // P as tf32 bits
            }
            lsum += __shfl_xor_sync(0xffffffffu, lsum, 1);
            lsum += __shfl_xor_sync(0xffffffffu, lsum, 2);
            if (q4 == 0) {
                sL[rrow] = sL[rrow] * alpha + lsum;
                sM[rrow] = mnew;
                sAl[rrow] = alpha;
            }
        }
        __syncthreads();

        // Rescale O accumulators by alpha.
        {
            float a0 = sAl[mo + g], a1 = sAl[mo + g + 8];
#pragma unroll
            for (int nt = 0; nt < 8; nt++) {
                o[nt][0] *= a0; o[nt][1] *= a0;
                o[nt][2] *= a1; o[nt][3] *= a1;
            }
        }

        // O += P . V over 128 (16 k-steps)
#pragma unroll
        for (int ks = 0; ks < 16; ks++) {
            const int kk = ks * 8;
            uint32_t af[4];
            af[0] = sS[(mo + g) * SS_STRIDE + kk + t4];
            af[1] = sS[(mo + g + 8) * SS_STRIDE + kk + t4];
            af[2] = sS[(mo + g) * SS_STRIDE + kk + t4 + 4];
            af[3] = sS[(mo + g + 8) * SS_STRIDE + kk + t4 + 4];
#pragma unroll
            for (int nt = 0; nt < 8; nt++) {
                uint32_t bf[2];
                int hc = ho + nt * 8 + g;
                bf[0] = sV[(kk + t4) * SV_STRIDE + hc];
                bf[1] = sV[(kk + t4 + 4) * SV_STRIDE + hc];
                mma_tf32(o[nt], af, bf);
            }
        }
        __syncthreads();
    }

    // Epilogue: normalize by l and store.
    const float il0 = 1.f / sL[mo + g];
    const float il1 = 1.f / sL[mo + g + 8];
    float* ob = out + ((size_t)b * T_DIM + i0 + mo) * H_DIM;
#pragma unroll
    for (int nt = 0; nt < 8; nt++) {
        int cc = ho + nt * 8 + 2 * t4;
        ob[(size_t)g * H_DIM + cc]           = o[nt][0] * il0;
        ob[(size_t)g * H_DIM + cc + 1]       = o[nt][1] * il0;
        ob[(size_t)(g + 8) * H_DIM + cc]     = o[nt][2] * il1;
        ob[(size_t)(g + 8) * H_DIM + cc + 1] = o[nt][3] * il1;
    }
}

extern "C" void kernel_launch(void* const* d_in, const int* in_sizes, int n_in,
                              void* d_out, int out_size)
{
    const float* idx = (const float*)d_in[0];
    const float* Wq  = (const float*)d_in[1];
    const float* Wk  = (const float*)d_in[2];
    const float* Wv  = (const float*)d_in[3];
    float* out = (float*)d_out;

    (void)in_sizes; (void)n_in; (void)out_size;

    cudaFuncSetAttribute(attn_kernel, cudaFuncAttributeMaxDynamicSharedMemorySize, SMEM_BYTES);

    proj_kernel<<<dim3(3, (B_DIM * T_DIM) / 128), 256>>>(idx, Wq, Wk, Wv);
    attn_kernel<<<dim3(T_DIM / 64, B_DIM), 256, SMEM_BYTES>>>(out);
}

// round 4
// speedup vs baseline: 1.0702x; 1.0008x over previous
#include <cuda_runtime.h>
#include <cstdint>

#define B_DIM 4
#define T_DIM 4096
#define C_DIM 2048
#define H_DIM 128

// Scratch for projected q, k, v: [B, T, H] fp32 each (8 MB each).
__device__ float g_q[(size_t)B_DIM * T_DIM * H_DIM];
__device__ float g_k[(size_t)B_DIM * T_DIM * H_DIM];
__device__ float g_v[(size_t)B_DIM * T_DIM * H_DIM];

__device__ __forceinline__ uint32_t f2tf32(float f) {
    uint32_t r;
    asm("cvt.rna.tf32.f32 %0, %1;" : "=r"(r) : "f"(f));
    return r;
}

// D = A(16x8, row) * B(8x8, col) + D, tf32 inputs, fp32 accum.
__device__ __forceinline__ void mma_tf32(float* c, const uint32_t* a, const uint32_t* b) {
    asm volatile(
        "mma.sync.aligned.m16n8k8.row.col.f32.tf32.tf32.f32 "
        "{%0,%1,%2,%3}, {%4,%5,%6,%7}, {%8,%9}, {%0,%1,%2,%3};\n"
        : "+f"(c[0]), "+f"(c[1]), "+f"(c[2]), "+f"(c[3])
        : "r"(a[0]), "r"(a[1]), "r"(a[2]), "r"(a[3]), "r"(b[0]), "r"(b[1]));
}

// ============================================================================
// Kernel 1: projections. out[m, h] = sum_c idx[m, c] * W[h, c]
// Block tile 128(M) x 128(N=H), K-chunk 32, smem double-buffered:
//   iter: LDG next chunk -> regs | MMA current buffer | cvt+STS next buffer
// grid = (3, M/128): the 3 sibling blocks (q/k/v of same rows) are adjacent
// bids -> concurrent -> idx rows hit L2.
// ============================================================================
#define PSTR 36  // 32 + 4 pad: conflict-free fragment loads

__global__ void __launch_bounds__(256) proj_kernel(
    const float* __restrict__ idx,
    const float* __restrict__ Wq,
    const float* __restrict__ Wk,
    const float* __restrict__ Wv)
{
    __shared__ uint32_t sA[2][128 * PSTR];
    __shared__ uint32_t sB[2][128 * PSTR];

    const int tid  = threadIdx.x;
    const int warp = tid >> 5, lane = tid & 31;
    const int g = lane >> 2, t4 = lane & 3;
    const int mo = (warp & 3) * 32;   // warp M offset
    const int no = (warp >> 2) * 64;  // warp N offset
    const int row0 = blockIdx.y * 128;
    const int wsel = blockIdx.x;

    const float* W = (wsel == 0) ? Wq : (wsel == 1 ? Wk : Wv);
    float* out = (wsel == 0) ? g_q : (wsel == 1 ? g_k : g_v);

    float acc[2][8][4];
#pragma unroll
    for (int i = 0; i < 2; i++)
#pragma unroll
        for (int j = 0; j < 8; j++)
#pragma unroll
            for (int l = 0; l < 4; l++) acc[i][j][l] = 0.f;

    // load map: 2 threads per row, 16 floats each
    const int lr = tid >> 1;
    const int lc = (tid & 1) * 16;
    const float* aptr = idx + (size_t)(row0 + lr) * C_DIM + lc;
    const float* bptr = W + (size_t)lr * C_DIM + lc;

    float4 pa[4], pb[4];

    // prologue: chunk 0
#pragma unroll
    for (int j = 0; j < 4; j++) {
        pa[j] = *reinterpret_cast<const float4*>(aptr + j * 4);
        pb[j] = *reinterpret_cast<const float4*>(bptr + j * 4);
    }
#pragma unroll
    for (int j = 0; j < 4; j++) {
        uint4 ua = { f2tf32(pa[j].x), f2tf32(pa[j].y), f2tf32(pa[j].z), f2tf32(pa[j].w) };
        uint4 ub = { f2tf32(pb[j].x), f2tf32(pb[j].y), f2tf32(pb[j].z), f2tf32(pb[j].w) };
        *reinterpret_cast<uint4*>(&sA[0][lr * PSTR + lc + j * 4]) = ua;
        *reinterpret_cast<uint4*>(&sB[0][lr * PSTR + lc + j * 4]) = ub;
    }
    __syncthreads();

    int cur = 0;
    for (int kb = 0; kb < C_DIM; kb += 32) {
        const bool more = (kb + 32) < C_DIM;
        if (more) {
#pragma unroll
            for (int j = 0; j < 4; j++) {
                pa[j] = *reinterpret_cast<const float4*>(aptr + kb + 32 + j * 4);
                pb[j] = *reinterpret_cast<const float4*>(bptr + kb + 32 + j * 4);
            }
        }

        const uint32_t* bufA = sA[cur];
        const uint32_t* bufB = sB[cur];
#pragma unroll
        for (int ks = 0; ks < 4; ks++) {
            const int kk = ks * 8;
            uint32_t af[2][4];
#pragma unroll
            for (int mt = 0; mt < 2; mt++) {
                int mr = mo + mt * 16;
                af[mt][0] = bufA[(mr + g) * PSTR + kk + t4];
                af[mt][1] = bufA[(mr + g + 8) * PSTR + kk + t4];
                af[mt][2] = bufA[(mr + g) * PSTR + kk + t4 + 4];
                af[mt][3] = bufA[(mr + g + 8) * PSTR + kk + t4 + 4];
            }
#pragma unroll
            for (int nt = 0; nt < 8; nt++) {
                uint32_t bf[2];
                int nc = no + nt * 8 + g;
                bf[0] = bufB[nc * PSTR + kk + t4];
                bf[1] = bufB[nc * PSTR + kk + t4 + 4];
                mma_tf32(acc[0][nt], af[0], bf);
                mma_tf32(acc[1][nt], af[1], bf);
            }
        }

        if (more) {
#pragma unroll
            for (int j = 0; j < 4; j++) {
                uint4 ua = { f2tf32(pa[j].x), f2tf32(pa[j].y), f2tf32(pa[j].z), f2tf32(pa[j].w) };
                uint4 ub = { f2tf32(pb[j].x), f2tf32(pb[j].y), f2tf32(pb[j].z), f2tf32(pb[j].w) };
                *reinterpret_cast<uint4*>(&sA[cur ^ 1][lr * PSTR + lc + j * 4]) = ua;
                *reinterpret_cast<uint4*>(&sB[cur ^ 1][lr * PSTR + lc + j * 4]) = ub;
            }
        }
        __syncthreads();
        cur ^= 1;
    }

#pragma unroll
    for (int mt = 0; mt < 2; mt++) {
#pragma unroll
        for (int nt = 0; nt < 8; nt++) {
            int r  = row0 + mo + mt * 16 + g;
            int cc = no + nt * 8 + 2 * t4;
            out[(size_t)r * H_DIM + cc]           = acc[mt][nt][0];
            out[(size_t)r * H_DIM + cc + 1]       = acc[mt][nt][1];
            out[(size_t)(r + 8) * H_DIM + cc]     = acc[mt][nt][2];
            out[(size_t)(r + 8) * H_DIM + cc + 1] = acc[mt][nt][3];
        }
    }
}

// ============================================================================
// Kernel 2: flash attention.
//   S[i, j] = scale * k_i . q_j   (rows = K, cols = Q per the reference)
//   causal j <= i, online softmax over j, O = P . V
// BM=64 rows(i) per block, BN=128 (j) per iteration. 256 threads, 8 warps.
// Blocks launched heavy-first (reversed i0) for load balance.
// ============================================================================
#define SK_STRIDE 132  // K/Q: row-major frag loads conflict-free
#define SV_STRIDE 136  // V: k-row-indexed frag loads conflict-free
#define SS_STRIDE 132  // S/P tile 64 x 128

#define SMEM_WORDS (64 * SK_STRIDE + 128 * SK_STRIDE + 128 * SV_STRIDE + 64 * SS_STRIDE + 3 * 64)
#define SMEM_BYTES (SMEM_WORDS * 4)

__global__ void __launch_bounds__(256, 1) attn_kernel(float* __restrict__ out)
{
    extern __shared__ uint32_t smbuf[];
    uint32_t* sK = smbuf;                       // 64 x SK_STRIDE
    uint32_t* sQ = sK + 64 * SK_STRIDE;         // 128 x SK_STRIDE
    uint32_t* sV = sQ + 128 * SK_STRIDE;        // 128 x SV_STRIDE
    uint32_t* sS = sV + 128 * SV_STRIDE;        // 64 x SS_STRIDE
    float* sM  = (float*)(sS + 64 * SS_STRIDE);
    float* sL  = sM + 64;
    float* sAl = sL + 64;

    const int tid  = threadIdx.x;
    const int warp = tid >> 5, lane = tid & 31;
    const int g = lane >> 2, t4 = lane & 3;
    const int i0 = (gridDim.x - 1 - blockIdx.x) * 64;  // heavy blocks first
    const int b  = blockIdx.y;
    const float scale = 0.022097086912079608f;  // 2048^-0.5
    const float NEG_INF = -__int_as_float(0x7f800000);

    // Load K tile (rows i0..i0+63), tf32.
    {
        const float* kb = g_k + ((size_t)b * T_DIM + i0) * H_DIM;
#pragma unroll 4
        for (int i = 0; i < 8; i++) {
            int idx4 = tid + i * 256;
            int r = idx4 >> 5;
            int c = (idx4 & 31) * 4;
            float4 f = *reinterpret_cast<const float4*>(kb + (size_t)r * H_DIM + c);
            sK[r * SK_STRIDE + c + 0] = f2tf32(f.x);
            sK[r * SK_STRIDE + c + 1] = f2tf32(f.y);
            sK[r * SK_STRIDE + c + 2] = f2tf32(f.z);
            sK[r * SK_STRIDE + c + 3] = f2tf32(f.w);
        }
    }
    if (tid < 64) { sM[tid] = NEG_INF; sL[tid] = 0.f; }

    const int mo = (warp & 3) * 16;   // M-row offset (S and O)
    const int so = (warp >> 2) * 64;  // S col offset (of 128)
    const int ho = (warp >> 2) * 64;  // O col offset (of 128)

    float o[8][4];
#pragma unroll
    for (int nt = 0; nt < 8; nt++)
#pragma unroll
        for (int l = 0; l < 4; l++) o[nt][l] = 0.f;

    const int rrow = tid >> 2;  // softmax row 0..63
    const int q4   = tid & 3;

    for (int j0 = 0; j0 <= i0; j0 += 128) {
        // Load Q, V tiles (128 rows each) for this j-tile.
        const float* qb = g_q + ((size_t)b * T_DIM + j0) * H_DIM;
        const float* vb = g_v + ((size_t)b * T_DIM + j0) * H_DIM;
#pragma unroll 4
        for (int i = 0; i < 16; i++) {
            int idx4 = tid + i * 256;
            int r = idx4 >> 5;
            int c = (idx4 & 31) * 4;
            float4 fq = *reinterpret_cast<const float4*>(qb + (size_t)r * H_DIM + c);
            float4 fv = *reinterpret_cast<const float4*>(vb + (size_t)r * H_DIM + c);
            sQ[r * SK_STRIDE + c + 0] = f2tf32(fq.x);
            sQ[r * SK_STRIDE + c + 1] = f2tf32(fq.y);
            sQ[r * SK_STRIDE + c + 2] = f2tf32(fq.z);
            sQ[r * SK_STRIDE + c + 3] = f2tf32(fq.w);
            sV[r * SV_STRIDE + c + 0] = f2tf32(fv.x);
            sV[r * SV_STRIDE + c + 1] = f2tf32(fv.y);
            sV[r * SV_STRIDE + c + 2] = f2tf32(fv.z);
            sV[r * SV_STRIDE + c + 3] = f2tf32(fv.w);
        }
        __syncthreads();

        // S = K . Q^T over H=128 (16 k-steps), S tile 64 x 128
        float s[8][4];
#pragma unroll
        for (int nt = 0; nt < 8; nt++)
#pragma unroll
            for (int l = 0; l < 4; l++) s[nt][l] = 0.f;

#pragma unroll
        for (int ks = 0; ks < 16; ks++) {
            const int kk = ks * 8;
            uint32_t af[4];
            af[0] = sK[(mo + g) * SK_STRIDE + kk + t4];
            af[1] = sK[(mo + g + 8) * SK_STRIDE + kk + t4];
            af[2] = sK[(mo + g) * SK_STRIDE + kk + t4 + 4];
            af[3] = sK[(mo + g + 8) * SK_STRIDE + kk + t4 + 4];
#pragma unroll
            for (int nt = 0; nt < 8; nt++) {
                uint32_t bf[2];
                int nc = so + nt * 8 + g;
                bf[0] = sQ[nc * SK_STRIDE + kk + t4];
                bf[1] = sQ[nc * SK_STRIDE + kk + t4 + 4];
                mma_tf32(s[nt], af, bf);
            }
        }
        // Scale and park S in shared (fp32 bits).
#pragma unroll
        for (int nt = 0; nt < 8; nt++) {
            int cc = so + nt * 8 + 2 * t4;
            sS[(mo + g) * SS_STRIDE + cc]         = __float_as_uint(s[nt][0] * scale);
            sS[(mo + g) * SS_STRIDE + cc + 1]     = __float_as_uint(s[nt][1] * scale);
            sS[(mo + g + 8) * SS_STRIDE + cc]     = __float_as_uint(s[nt][2] * scale);
            sS[(mo + g + 8) * SS_STRIDE + cc + 1] = __float_as_uint(s[nt][3] * scale);
        }
        __syncthreads();

        // Online softmax: 4 threads per row, 32 cols each.
        {
            float sv[32];
            float mloc = NEG_INF;
            const int gi = i0 + rrow;
#pragma unroll
            for (int t = 0; t < 32; t++) {
                int c = q4 + t * 4;
                float val = __uint_as_float(sS[rrow * SS_STRIDE + c]);
                bool valid = (j0 + c) <= gi;
                sv[t] = valid ? val : NEG_INF;
                mloc = fmaxf(mloc, sv[t]);
            }
            mloc = fmaxf(mloc, __shfl_xor_sync(0xffffffffu, mloc, 1));
            mloc = fmaxf(mloc, __shfl_xor_sync(0xffffffffu, mloc, 2));
            float mprev = sM[rrow];
            float mnew  = fmaxf(mprev, mloc);
            float alpha = __expf(mprev - mnew);
            float lsum = 0.f;
#pragma unroll
            for (int t = 0; t < 32; t++) {
                int c = q4 + t * 4;
                float p = __expf(sv[t] - mnew);
                lsum += p;
                sS[rrow * SS_STRIDE + c] = f2tf32(p);  // P as tf32 bits
            }
            lsum += __shfl_xor_sync(0xffffffffu, lsum, 1);
            lsum += __shfl_xor_sync(0xffffffffu, lsum, 2);
            if (q4 == 0) {
                sL[rrow] = sL[rrow] * alpha + lsum;
                sM[rrow] = mnew;
                sAl[rrow] = alpha;
            }
        }
        __syncthreads();

        // Rescale O accumulators by alpha.
        {
            float a0 = sAl[mo + g], a1 = sAl[mo + g + 8];
#pragma unroll
            for (int nt = 0; nt < 8; nt++) {
                o[nt][0] *= a0; o[nt][1] *= a0;
                o[nt][2] *= a1; o[nt][3] *= a1;
            }
        }

        // O += P . V over 128 (16 k-steps)
#pragma unroll
        for (int ks = 0; ks < 16; ks++) {
            const int kk = ks * 8;
            uint32_t af[4];
            af[0] = sS[(mo + g) * SS_STRIDE + kk + t4];
            af[1] = sS[(mo + g + 8) * SS_STRIDE + kk + t4];
            af[2] = sS[(mo + g) * SS_STRIDE + kk + t4 + 4];
            af[3] = sS[(mo + g + 8) * SS_STRIDE + kk + t4 + 4];
#pragma unroll
            for (int nt = 0; nt < 8; nt++) {
                uint32_t bf[2];
                int hc = ho + nt * 8 + g;
                bf[0] = sV[(kk + t4) * SV_STRIDE + hc];
                bf[1] = sV[(kk + t4 + 4) * SV_STRIDE + hc];
                mma_tf32(o[nt], af, bf);
            }
        }
        __syncthreads();
    }

    // Epilogue: normalize by l and store.
    const float il0 = 1.f / sL[mo + g];
    const float il1 = 1.f / sL[mo + g + 8];
    float* ob = out + ((size_t)b * T_DIM + i0 + mo) * H_DIM;
#pragma unroll
    for (int nt = 0; nt < 8; nt++) {
        int cc = ho + nt * 8 + 2 * t4;
        ob[(size_t)g * H_DIM + cc]           = o[nt][0] * il0;
        ob[(size_t)g * H_DIM + cc + 1]       = o[nt][1] * il0;
        ob[(size_t)(g + 8) * H_DIM + cc]     = o[nt][2] * il1;
        ob[(size_t)(g + 8) * H_DIM + cc + 1] = o[nt][3] * il1;
    }
}

extern "C" void kernel_launch(void* const* d_in, const int* in_sizes, int n_in,
                              void* d_out, int out_size)
{
    const float* idx = (const float*)d_in[0];
    const float* Wq  = (const float*)d_in[1];
    const float* Wk  = (const float*)d_in[2];
    const float* Wv  = (const float*)d_in[3];
    float* out = (float*)d_out;

    (void)in_sizes; (void)n_in; (void)out_size;

    cudaFuncSetAttribute(attn_kernel, cudaFuncAttributeMaxDynamicSharedMemorySize, SMEM_BYTES);

    proj_kernel<<<dim3(3, (B_DIM * T_DIM) / 128), 256>>>(idx, Wq, Wk, Wv);
    attn_kernel<<<dim3(T_DIM / 64, B_DIM), 256, SMEM_BYTES>>>(out);
}

// round 5
// speedup vs baseline: 1.2848x; 1.2005x over previous
#include <cuda_runtime.h>
#include <cstdint>

#define B_DIM 4
#define T_DIM 4096
#define C_DIM 2048
#define H_DIM 128

__device__ float g_q[(size_t)B_DIM * T_DIM * H_DIM];
__device__ float g_k[(size_t)B_DIM * T_DIM * H_DIM];
__device__ float g_v[(size_t)B_DIM * T_DIM * H_DIM];
// split-K partials: 4 batches x 64 row-blocks x 8 chunks
__device__ float  g_po[(size_t)2048 * 8192];   // O partials [64][128]
__device__ float2 g_ml[(size_t)2048 * 64];     // per-row (m, l)

__device__ __forceinline__ uint32_t f2tf32(float f) {
    uint32_t r;
    asm("cvt.rna.tf32.f32 %0, %1;" : "=r"(r) : "f"(f));
    return r;
}
__device__ __forceinline__ float tf32r(float f) { return __uint_as_float(f2tf32(f)); }

__device__ __forceinline__ void mma_tf32(float* c, const uint32_t* a, const uint32_t* b) {
    asm volatile(
        "mma.sync.aligned.m16n8k8.row.col.f32.tf32.tf32.f32 "
        "{%0,%1,%2,%3}, {%4,%5,%6,%7}, {%8,%9}, {%0,%1,%2,%3};\n"
        : "+f"(c[0]), "+f"(c[1]), "+f"(c[2]), "+f"(c[3])
        : "r"(a[0]), "r"(a[1]), "r"(a[2]), "r"(a[3]), "r"(b[0]), "r"(b[1]));
}

__device__ __forceinline__ uint32_t smem_u32(const void* p) {
    return (uint32_t)__cvta_generic_to_shared(p);
}
__device__ __forceinline__ void cp_async16(uint32_t dst, const void* src) {
    asm volatile("cp.async.cg.shared.global [%0], [%1], 16;\n" :: "r"(dst), "l"(src) : "memory");
}
__device__ __forceinline__ void cp_commit() { asm volatile("cp.async.commit_group;\n" ::: "memory"); }
__device__ __forceinline__ void cp_wait0()  { asm volatile("cp.async.wait_group 0;\n" ::: "memory"); }

// ============================================================================
// Kernel 1: projections (unchanged from R2 except tf32-rounded epilogue).
// ============================================================================
#define PSTR 36

__global__ void __launch_bounds__(256) proj_kernel(
    const float* __restrict__ idx, const float* __restrict__ Wq,
    const float* __restrict__ Wk,  const float* __restrict__ Wv)
{
    __shared__ uint32_t sA[2][128 * PSTR];
    __shared__ uint32_t sB[2][128 * PSTR];

    const int tid  = threadIdx.x;
    const int warp = tid >> 5, lane = tid & 31;
    const int g = lane >> 2, t4 = lane & 3;
    const int mo = (warp & 3) * 32, no = (warp >> 2) * 64;
    const int row0 = blockIdx.y * 128;
    const int wsel = blockIdx.x;

    const float* W = (wsel == 0) ? Wq : (wsel == 1 ? Wk : Wv);
    float* out = (wsel == 0) ? g_q : (wsel == 1 ? g_k : g_v);

    float acc[2][8][4] = {};
    const int lr = tid >> 1;
    const int lc = (tid & 1) * 16;
    const float* aptr = idx + (size_t)(row0 + lr) * C_DIM + lc;
    const float* bptr = W + (size_t)lr * C_DIM + lc;

    float4 pa[4], pb[4];
#pragma unroll
    for (int j = 0; j < 4; j++) {
        pa[j] = *reinterpret_cast<const float4*>(aptr + j * 4);
        pb[j] = *reinterpret_cast<const float4*>(bptr + j * 4);
    }
#pragma unroll
    for (int j = 0; j < 4; j++) {
        uint4 ua = { f2tf32(pa[j].x), f2tf32(pa[j].y), f2tf32(pa[j].z), f2tf32(pa[j].w) };
        uint4 ub = { f2tf32(pb[j].x), f2tf32(pb[j].y), f2tf32(pb[j].z), f2tf32(pb[j].w) };
        *reinterpret_cast<uint4*>(&sA[0][lr * PSTR + lc + j * 4]) = ua;
        *reinterpret_cast<uint4*>(&sB[0][lr * PSTR + lc + j * 4]) = ub;
    }
    __syncthreads();

    int cur = 0;
    for (int kb = 0; kb < C_DIM; kb += 32) {
        const bool more = (kb + 32) < C_DIM;
        if (more) {
#pragma unroll
            for (int j = 0; j < 4; j++) {
                pa[j] = *reinterpret_cast<const float4*>(aptr + kb + 32 + j * 4);
                pb[j] = *reinterpret_cast<const float4*>(bptr + kb + 32 + j * 4);
            }
        }
        const uint32_t* bufA = sA[cur];
        const uint32_t* bufB = sB[cur];
#pragma unroll
        for (int ks = 0; ks < 4; ks++) {
            const int kk = ks * 8;
            uint32_t af[2][4];
#pragma unroll
            for (int mt = 0; mt < 2; mt++) {
                int mr = mo + mt * 16;
                af[mt][0] = bufA[(mr + g) * PSTR + kk + t4];
                af[mt][1] = bufA[(mr + g + 8) * PSTR + kk + t4];
                af[mt][2] = bufA[(mr + g) * PSTR + kk + t4 + 4];
                af[mt][3] = bufA[(mr + g + 8) * PSTR + kk + t4 + 4];
            }
#pragma unroll
            for (int nt = 0; nt < 8; nt++) {
                int nc = no + nt * 8 + g;
                uint32_t bf[2] = { bufB[nc * PSTR + kk + t4], bufB[nc * PSTR + kk + t4 + 4] };
                mma_tf32(acc[0][nt], af[0], bf);
                mma_tf32(acc[1][nt], af[1], bf);
            }
        }
        if (more) {
#pragma unroll
            for (int j = 0; j < 4; j++) {
                uint4 ua = { f2tf32(pa[j].x), f2tf32(pa[j].y), f2tf32(pa[j].z), f2tf32(pa[j].w) };
                uint4 ub = { f2tf32(pb[j].x), f2tf32(pb[j].y), f2tf32(pb[j].z), f2tf32(pb[j].w) };
                *reinterpret_cast<uint4*>(&sA[cur ^ 1][lr * PSTR + lc + j * 4]) = ua;
                *reinterpret_cast<uint4*>(&sB[cur ^ 1][lr * PSTR + lc + j * 4]) = ub;
            }
        }
        __syncthreads();
        cur ^= 1;
    }

#pragma unroll
    for (int mt = 0; mt < 2; mt++) {
#pragma unroll
        for (int nt = 0; nt < 8; nt++) {
            int r  = row0 + mo + mt * 16 + g;
            int cc = no + nt * 8 + 2 * t4;
            out[(size_t)r * H_DIM + cc]           = tf32r(acc[mt][nt][0]);
            out[(size_t)r * H_DIM + cc + 1]       = tf32r(acc[mt][nt][1]);
            out[(size_t)(r + 8) * H_DIM + cc]     = tf32r(acc[mt][nt][2]);
            out[(size_t)(r + 8) * H_DIM + cc + 1] = tf32r(acc[mt][nt][3]);
        }
    }
}

// ============================================================================
// Kernel 2: split-K flash attention partials.
// S[i,j] = scale*k_i.q_j, causal j<=i. BM=64 rows, chunk = 8 tiles of 64 cols.
// grid (8 chunks, 64 row-blocks heavy-first, 4 batches), 256 thr, 2 CTAs/SM.
// S in registers through softmax; P (tf32) aliases dead Q buffer.
// ============================================================================
#define KSTR 132
#define VSTR 136
#define PST2 68
#define OQ   (64 * KSTR)
#define OV   (OQ + 64 * KSTR)
#define ORM  (OV + 64 * VSTR)
#define ORS  (ORM + 128)
#define OM_  (ORS + 128)
#define OL_  (OM_ + 64)
#define ATT_BYTES ((OL_ + 64) * 4)

__global__ void __launch_bounds__(256, 2) attn_kernel()
{
    extern __shared__ uint32_t sm[];
    uint32_t* sK = sm;
    uint32_t* sQ = sm + OQ;
    uint32_t* sV = sm + OV;
    uint32_t* sP = sQ;  // alias
    float* sRM = (float*)(sm + ORM);
    float* sRS = (float*)(sm + ORS);
    float* sM  = (float*)(sm + OM_);
    float* sL  = (float*)(sm + OL_);

    const int m = 63 - blockIdx.y;  // heavy first
    const int c = blockIdx.x;
    if (c * 8 > m) return;
    const int b = blockIdx.z;
    const int i0 = m * 64;
    const int jstart = c * 512;
    const int ntiles = min(8, m + 1 - c * 8);

    const int tid  = threadIdx.x;
    const int warp = tid >> 5, lane = tid & 31;
    const int g = lane >> 2, t4 = lane & 3;
    const int wm = warp & 3, wn = warp >> 2;
    const int mo = wm * 16, so = wn * 32, ho = wn * 64;
    const float scale = 0.022097086912079608f;
    const float NEGINF = __int_as_float(0xff800000);

    const float* kg = g_k + ((size_t)b * T_DIM + i0) * H_DIM;
    const float* qg = g_q + (size_t)b * T_DIM * H_DIM;
    const float* vg = g_v + (size_t)b * T_DIM * H_DIM;

#pragma unroll
    for (int t = 0; t < 8; t++) {
        int id = tid + t * 256;
        int r = id >> 5, gr = id & 31;
        cp_async16(smem_u32(sK + r * KSTR + gr * 4), kg + (size_t)r * H_DIM + gr * 4);
    }
    {
        const float* q0 = qg + (size_t)jstart * H_DIM;
        const float* v0 = vg + (size_t)jstart * H_DIM;
#pragma unroll
        for (int t = 0; t < 8; t++) {
            int id = tid + t * 256;
            int r = id >> 5, gr = id & 31;
            cp_async16(smem_u32(sQ + r * KSTR + gr * 4), q0 + (size_t)r * H_DIM + gr * 4);
            cp_async16(smem_u32(sV + r * VSTR + gr * 4), v0 + (size_t)r * H_DIM + gr * 4);
        }
    }
    cp_commit();
    if (tid < 64) { sM[tid] = NEGINF; sL[tid] = 0.f; }
    cp_wait0();
    __syncthreads();

    float o[8][4] = {};

    for (int t = 0; t < ntiles; t++) {
        const int j0 = jstart + t * 64;

        // S = K . Q^T, warp tile 16x32, registers
        float s[4][4] = {};
#pragma unroll
        for (int ks = 0; ks < 16; ks++) {
            const int kk = ks * 8;
            const uint32_t* kr = sK + (mo + g) * KSTR + kk + t4;
            uint32_t af[4] = { kr[0], kr[8 * KSTR], kr[4], kr[8 * KSTR + 4] };
#pragma unroll
            for (int nt = 0; nt < 4; nt++) {
                const uint32_t* qr = sQ + (so + nt * 8 + g) * KSTR + kk + t4;
                uint32_t bf[2] = { qr[0], qr[4] };
                mma_tf32(s[nt], af, bf);
            }
        }

        const int r0 = i0 + mo + g, r1 = r0 + 8;
        if (j0 == i0) {
#pragma unroll
            for (int nt = 0; nt < 4; nt++) {
                int c0 = j0 + so + nt * 8 + 2 * t4;
                s[nt][0] = (c0     <= r0) ? s[nt][0] * scale : NEGINF;
                s[nt][1] = (c0 + 1 <= r0) ? s[nt][1] * scale : NEGINF;
                s[nt][2] = (c0     <= r1) ? s[nt][2] * scale : NEGINF;
                s[nt][3] = (c0 + 1 <= r1) ? s[nt][3] * scale : NEGINF;
            }
        } else {
#pragma unroll
            for (int nt = 0; nt < 4; nt++) {
                s[nt][0] *= scale; s[nt][1] *= scale;
                s[nt][2] *= scale; s[nt][3] *= scale;
            }
        }

        // row maxes: thread -> quad -> cross n-warp via smem
        float mx0 = NEGINF, mx1 = NEGINF;
#pragma unroll
        for (int nt = 0; nt < 4; nt++) {
            mx0 = fmaxf(mx0, fmaxf(s[nt][0], s[nt][1]));
            mx1 = fmaxf(mx1, fmaxf(s[nt][2], s[nt][3]));
        }
        mx0 = fmaxf(mx0, __shfl_xor_sync(0xffffffffu, mx0, 1));
        mx0 = fmaxf(mx0, __shfl_xor_sync(0xffffffffu, mx0, 2));
        mx1 = fmaxf(mx1, __shfl_xor_sync(0xffffffffu, mx1, 1));
        mx1 = fmaxf(mx1, __shfl_xor_sync(0xffffffffu, mx1, 2));
        if (t4 == 0) {
            sRM[wn * 64 + mo + g]     = mx0;
            sRM[wn * 64 + mo + g + 8] = mx1;
        }
        __syncthreads();

        const float mo0 = sM[mo + g], mo1 = sM[mo + g + 8];
        const float mn0 = fmaxf(mo0, fmaxf(mx0, sRM[(wn ^ 1) * 64 + mo + g]));
        const float mn1 = fmaxf(mo1, fmaxf(mx1, sRM[(wn ^ 1) * 64 + mo + g + 8]));
        const float al0 = __expf(mo0 - mn0), al1 = __expf(mo1 - mn1);

        float su0 = 0.f, su1 = 0.f;
#pragma unroll
        for (int nt = 0; nt < 4; nt++) {
            float p0 = __expf(s[nt][0] - mn0), p1 = __expf(s[nt][1] - mn0);
            float p2 = __expf(s[nt][2] - mn1), p3 = __expf(s[nt][3] - mn1);
            su0 += p0 + p1; su1 += p2 + p3;
            uint32_t* pr = sP + (mo + g) * PST2 + so + nt * 8 + 2 * t4;
            pr[0] = f2tf32(p0); pr[1] = f2tf32(p1);
            pr[8 * PST2] = f2tf32(p2); pr[8 * PST2 + 1] = f2tf32(p3);
        }
        su0 += __shfl_xor_sync(0xffffffffu, su0, 1);
        su0 += __shfl_xor_sync(0xffffffffu, su0, 2);
        su1 += __shfl_xor_sync(0xffffffffu, su1, 1);
        su1 += __shfl_xor_sync(0xffffffffu, su1, 2);
        if (t4 == 0) {
            sRS[wn * 64 + mo + g]     = su0;
            sRS[wn * 64 + mo + g + 8] = su1;
        }
        __syncthreads();

        if (wn == 0 && t4 == 0) {
            sL[mo + g]     = sL[mo + g]     * al0 + su0 + sRS[64 + mo + g];
            sM[mo + g]     = mn0;
            sL[mo + g + 8] = sL[mo + g + 8] * al1 + su1 + sRS[64 + mo + g + 8];
            sM[mo + g + 8] = mn1;
        }

#pragma unroll
        for (int nt = 0; nt < 8; nt++) {
            o[nt][0] *= al0; o[nt][1] *= al0;
            o[nt][2] *= al1; o[nt][3] *= al1;
        }
#pragma unroll
        for (int ks = 0; ks < 8; ks++) {
            const int kk = ks * 8;
            const uint32_t* pr = sP + (mo + g) * PST2 + kk + t4;
            uint32_t af[4] = { pr[0], pr[8 * PST2], pr[4], pr[8 * PST2 + 4] };
#pragma unroll
            for (int nt = 0; nt < 8; nt++) {
                int vc = ho + nt * 8 + g;
                uint32_t bf[2] = { sV[(kk + t4) * VSTR + vc], sV[(kk + t4 + 4) * VSTR + vc] };
                mma_tf32(o[nt], af, bf);
            }
        }
        __syncthreads();

        if (t + 1 < ntiles) {
            const float* q0 = qg + (size_t)(j0 + 64) * H_DIM;
            const float* v0 = vg + (size_t)(j0 + 64) * H_DIM;
#pragma unroll
            for (int tt = 0; tt < 8; tt++) {
                int id = tid + tt * 256;
                int r = id >> 5, gr = id & 31;
                cp_async16(smem_u32(sQ + r * KSTR + gr * 4), q0 + (size_t)r * H_DIM + gr * 4);
                cp_async16(smem_u32(sV + r * VSTR + gr * 4), v0 + (size_t)r * H_DIM + gr * 4);
            }
            cp_commit();
            cp_wait0();
            __syncthreads();
        }
    }

    // write partials
    const size_t p = ((size_t)(b * 64 + m)) * 8 + c;
    float* po = g_po + p * 8192;
#pragma unroll
    for (int nt = 0; nt < 8; nt++) {
        int cc = ho + nt * 8 + 2 * t4;
        *reinterpret_cast<float2*>(&po[(mo + g) * 128 + cc])     = make_float2(o[nt][0], o[nt][1]);
        *reinterpret_cast<float2*>(&po[(mo + g + 8) * 128 + cc]) = make_float2(o[nt][2], o[nt][3]);
    }
    __syncthreads();
    if (tid < 64) g_ml[p * 64 + tid] = make_float2(sM[tid], sL[tid]);
}

// ============================================================================
// Kernel 3: merge split-K partials.
// ============================================================================
__global__ void __launch_bounds__(256) merge_kernel(float* __restrict__ out)
{
    const int m = blockIdx.x, b = blockIdx.y;
    const int nch = (m >> 3) + 1;
    const int r  = threadIdx.x >> 2;
    const int cg = threadIdx.x & 3;
    const size_t pb = ((size_t)(b * 64 + m)) * 8;

    float mst = __int_as_float(0xff800000);
    float wts[8];
#pragma unroll 1
    for (int c = 0; c < nch; c++)
        mst = fmaxf(mst, g_ml[(pb + c) * 64 + r].x);
    float den = 0.f;
#pragma unroll 1
    for (int c = 0; c < nch; c++) {
        float2 ml = g_ml[(pb + c) * 64 + r];
        wts[c] = __expf(ml.x - mst);
        den += wts[c] * ml.y;
    }
    const float inv = 1.f / den;

    float* orow = out + ((size_t)b * T_DIM + m * 64 + r) * H_DIM + cg * 32;
#pragma unroll
    for (int q = 0; q < 8; q++) {
        float4 acc = make_float4(0.f, 0.f, 0.f, 0.f);
#pragma unroll 1
        for (int c = 0; c < nch; c++) {
            const float* po = g_po + (pb + c) * 8192 + (size_t)r * 128 + cg * 32 + q * 4;
            float4 v = *reinterpret_cast<const float4*>(po);
            acc.x += wts[c] * v.x; acc.y += wts[c] * v.y;
            acc.z += wts[c] * v.z; acc.w += wts[c] * v.w;
        }
        acc.x *= inv; acc.y *= inv; acc.z *= inv; acc.w *= inv;
        *reinterpret_cast<float4*>(orow + q * 4) = acc;
    }
}

extern "C" void kernel_launch(void* const* d_in, const int* in_sizes, int n_in,
                              void* d_out, int out_size)
{
    const float* idx = (const float*)d_in[0];
    const float* Wq  = (const float*)d_in[1];
    const float* Wk  = (const float*)d_in[2];
    const float* Wv  = (const float*)d_in[3];
    float* out = (float*)d_out;
    (void)in_sizes; (void)n_in; (void)out_size;

    cudaFuncSetAttribute(attn_kernel, cudaFuncAttributeMaxDynamicSharedMemorySize, ATT_BYTES);

    proj_kernel<<<dim3(3, (B_DIM * T_DIM) / 128), 256>>>(idx, Wq, Wk, Wv);
    attn_kernel<<<dim3(8, 64, B_DIM), 256, ATT_BYTES>>>();
    merge_kernel<<<dim3(64, B_DIM), 256>>>(out);
}

// round 7
// speedup vs baseline: 1.3939x; 1.0849x over previous
#include <cuda_runtime.h>
#include <cstdint>

#define B_DIM 4
#define T_DIM 4096
#define C_DIM 2048
#define H_DIM 128

__device__ float g_q[(size_t)B_DIM * T_DIM * H_DIM];
__device__ float g_k[(size_t)B_DIM * T_DIM * H_DIM];
__device__ float g_v[(size_t)B_DIM * T_DIM * H_DIM];
__device__ float g_w[3 * H_DIM * C_DIM];       // W pre-rounded to tf32
// split-K partials: 4 batches x 64 row-blocks x 8 chunks
__device__ float  g_po[(size_t)2048 * 8192];   // O partials [64][128]
__device__ float2 g_ml[(size_t)2048 * 64];     // per-row (m, l)

__device__ __forceinline__ uint32_t f2tf32(float f) {
    uint32_t r;
    asm("cvt.rna.tf32.f32 %0, %1;" : "=r"(r) : "f"(f));
    return r;
}
__device__ __forceinline__ float tf32r(float f) { return __uint_as_float(f2tf32(f)); }

__device__ __forceinline__ void mma_tf32(float* c, const uint32_t* a, const uint32_t* b) {
    asm volatile(
        "mma.sync.aligned.m16n8k8.row.col.f32.tf32.tf32.f32 "
        "{%0,%1,%2,%3}, {%4,%5,%6,%7}, {%8,%9}, {%0,%1,%2,%3};\n"
        : "+f"(c[0]), "+f"(c[1]), "+f"(c[2]), "+f"(c[3])
        : "r"(a[0]), "r"(a[1]), "r"(a[2]), "r"(a[3]), "r"(b[0]), "r"(b[1]));
}

__device__ __forceinline__ uint32_t smem_u32(const void* p) {
    return (uint32_t)__cvta_generic_to_shared(p);
}
__device__ __forceinline__ void cp_async16(uint32_t dst, const void* src) {
    asm volatile("cp.async.cg.shared.global [%0], [%1], 16;\n" :: "r"(dst), "l"(src) : "memory");
}
__device__ __forceinline__ void cp_commit() { asm volatile("cp.async.commit_group;\n" ::: "memory"); }
__device__ __forceinline__ void cp_wait0()  { asm volatile("cp.async.wait_group 0;\n" ::: "memory"); }
__device__ __forceinline__ void cp_wait2()  { asm volatile("cp.async.wait_group 2;\n" ::: "memory"); }

// swizzled word index in a row-major [rows x 32-word] tile (16B granules)
__device__ __forceinline__ int swz(int r, int w) {
    return r * 32 + (((w >> 2) ^ (r & 7)) << 2) + (w & 3);
}

// ============================================================================
// Kernel 0: W -> tf32-rounded copy (3 x [128,2048]).
// ============================================================================
__global__ void cvtw_kernel(const float* __restrict__ Wq,
                            const float* __restrict__ Wk,
                            const float* __restrict__ Wv)
{
    const int per = H_DIM * C_DIM;
    int i = (blockIdx.x * 256 + threadIdx.x) * 4;
    const float* src = (i < per) ? Wq : (i < 2 * per ? Wk : Wv);
    float4 v = *reinterpret_cast<const float4*>(&src[i % per]);
    float4 r = { tf32r(v.x), tf32r(v.y), tf32r(v.z), tf32r(v.w) };
    *reinterpret_cast<float4*>(&g_w[i]) = r;
}

// ============================================================================
// Kernel 1: projections, 3-stage cp.async pipeline, 64x128 tile, 3 CTAs/SM.
// A (idx rows) staged raw fp32, rounded to tf32 in-register; B from g_w.
// grid (3 wsel fastest, 256 row-blocks) so q/k/v siblings share idx in L2.
// ============================================================================
#define PJ_STAGE_W (192 * 32)            // 64 A-rows + 128 B-rows, 32 words each
#define PJ_BYTES   (3 * PJ_STAGE_W * 4)  // 73728 B

__global__ void __launch_bounds__(256, 3) proj_kernel(const float* __restrict__ idx)
{
    extern __shared__ uint32_t ps[];

    const int tid  = threadIdx.x;
    const int warp = tid >> 5, lane = tid & 31;
    const int g = lane >> 2, t4 = lane & 3;
    const int wm = warp >> 2, wn = warp & 3;     // 2 x 4 warp grid
    const int mo = wm * 32, no = wn * 32;        // warp tile 32 x 32
    const int row0 = blockIdx.y * 64;
    const int wsel = blockIdx.x;

    const float* A  = idx + (size_t)row0 * C_DIM;
    const float* Bw = g_w + (size_t)wsel * (H_DIM * C_DIM);
    float* out = (wsel == 0) ? g_q : (wsel == 1 ? g_k : g_v);

    // A: 64 rows x 8 granules = 512 -> 2/thread; B: 128 x 8 = 1024 -> 4/thread
    auto issue = [&](int chunk) {
        const int kb = chunk * 32;
        uint32_t* st = ps + (chunk % 3) * PJ_STAGE_W;
#pragma unroll
        for (int t = 0; t < 2; t++) {
            int id = tid + t * 256;
            int r = id >> 3, gr = id & 7;
            cp_async16(smem_u32(st + r * 32 + ((gr ^ (r & 7)) << 2)),
                       A + (size_t)r * C_DIM + kb + gr * 4);
        }
        uint32_t* stB = st + 64 * 32;
#pragma unroll
        for (int t = 0; t < 4; t++) {
            int id = tid + t * 256;
            int r = id >> 3, gr = id & 7;
            cp_async16(smem_u32(stB + r * 32 + ((gr ^ (r & 7)) << 2)),
                       Bw + (size_t)r * C_DIM + kb + gr * 4);
        }
        cp_commit();
    };

    float acc[2][4][4] = {};

    issue(0); issue(1); issue(2);

    for (int k = 0; k < 64; k++) {
        cp_wait2();
        __syncthreads();
        const uint32_t* bA = ps + (k % 3) * PJ_STAGE_W;
        const uint32_t* bB = bA + 64 * 32;
#pragma unroll
        for (int ks = 0; ks < 4; ks++) {
            const int kk = ks * 8;
            uint32_t af[2][4];
#pragma unroll
            for (int mt = 0; mt < 2; mt++) {
                int r0 = mo + mt * 16 + g;
                af[mt][0] = f2tf32(__uint_as_float(bA[swz(r0,     kk + t4)]));
                af[mt][1] = f2tf32(__uint_as_float(bA[swz(r0 + 8, kk + t4)]));
                af[mt][2] = f2tf32(__uint_as_float(bA[swz(r0,     kk + t4 + 4)]));
                af[mt][3] = f2tf32(__uint_as_float(bA[swz(r0 + 8, kk + t4 + 4)]));
            }
#pragma unroll
            for (int nt = 0; nt < 4; nt++) {
                int nc = no + nt * 8 + g;
                uint32_t bf[2] = { bB[swz(nc, kk + t4)], bB[swz(nc, kk + t4 + 4)] };
                mma_tf32(acc[0][nt], af[0], bf);
                mma_tf32(acc[1][nt], af[1], bf);
            }
        }
        __syncthreads();
        if (k + 3 < 64) issue(k + 3);
        else cp_commit();  // keep group count aligned for cp_wait2
    }

#pragma unroll
    for (int mt = 0; mt < 2; mt++) {
#pragma unroll
        for (int nt = 0; nt < 4; nt++) {
            int r  = row0 + mo + mt * 16 + g;
            int cc = no + nt * 8 + 2 * t4;
            out[(size_t)r * H_DIM + cc]           = tf32r(acc[mt][nt][0]);
            out[(size_t)r * H_DIM + cc + 1]       = tf32r(acc[mt][nt][1]);
            out[(size_t)(r + 8) * H_DIM + cc]     = tf32r(acc[mt][nt][2]);
            out[(size_t)(r + 8) * H_DIM + cc + 1] = tf32r(acc[mt][nt][3]);
        }
    }
}

// ============================================================================
// Kernel 2: split-K flash attention partials (unchanged from R4).
// ============================================================================
#define KSTR 132
#define VSTR 136
#define PST2 68
#define OQ   (64 * KSTR)
#define OV   (OQ + 64 * KSTR)
#define ORM  (OV + 64 * VSTR)
#define ORS  (ORM + 128)
#define OM_  (ORS + 128)
#define OL_  (OM_ + 64)
#define ATT_BYTES ((OL_ + 64) * 4)

__global__ void __launch_bounds__(256, 2) attn_kernel()
{
    extern __shared__ uint32_t sm[];
    uint32_t* sK = sm;
    uint32_t* sQ = sm + OQ;
    uint32_t* sV = sm + OV;
    uint32_t* sP = sQ;  // alias
    float* sRM = (float*)(sm + ORM);
    float* sRS = (float*)(sm + ORS);
    float* sM  = (float*)(sm + OM_);
    float* sL  = (float*)(sm + OL_);

    const int m = 63 - blockIdx.y;  // heavy first
    const int c = blockIdx.x;
    if (c * 8 > m) return;
    const int b = blockIdx.z;
    const int i0 = m * 64;
    const int jstart = c * 512;
    const int ntiles = min(8, m + 1 - c * 8);

    const int tid  = threadIdx.x;
    const int warp = tid >> 5, lane = tid & 31;
    const int g = lane >> 2, t4 = lane & 3;
    const int wm = warp & 3, wn = warp >> 2;
    const int mo = wm * 16, so = wn * 32, ho = wn * 64;
    const float scale = 0.022097086912079608f;
    const float NEGINF = __int_as_float(0xff800000);

    const float* kg = g_k + ((size_t)b * T_DIM + i0) * H_DIM;
    const float* qg = g_q + (size_t)b * T_DIM * H_DIM;
    const float* vg = g_v + (size_t)b * T_DIM * H_DIM;

#pragma unroll
    for (int t = 0; t < 8; t++) {
        int id = tid + t * 256;
        int r = id >> 5, gr = id & 31;
        cp_async16(smem_u32(sK + r * KSTR + gr * 4), kg + (size_t)r * H_DIM + gr * 4);
    }
    {
        const float* q0 = qg + (size_t)jstart * H_DIM;
        const float* v0 = vg + (size_t)jstart * H_DIM;
#pragma unroll
        for (int t = 0; t < 8; t++) {
            int id = tid + t * 256;
            int r = id >> 5, gr = id & 31;
            cp_async16(smem_u32(sQ + r * KSTR + gr * 4), q0 + (size_t)r * H_DIM + gr * 4);
            cp_async16(smem_u32(sV + r * VSTR + gr * 4), v0 + (size_t)r * H_DIM + gr * 4);
        }
    }
    cp_commit();
    if (tid < 64) { sM[tid] = NEGINF; sL[tid] = 0.f; }
    cp_wait0();
    __syncthreads();

    float o[8][4] = {};

    for (int t = 0; t < ntiles; t++) {
        const int j0 = jstart + t * 64;

        float s[4][4] = {};
#pragma unroll
        for (int ks = 0; ks < 16; ks++) {
            const int kk = ks * 8;
            const uint32_t* kr = sK + (mo + g) * KSTR + kk + t4;
            uint32_t af[4] = { kr[0], kr[8 * KSTR], kr[4], kr[8 * KSTR + 4] };
#pragma unroll
            for (int nt = 0; nt < 4; nt++) {
                const uint32_t* qr = sQ + (so + nt * 8 + g) * KSTR + kk + t4;
                uint32_t bf[2] = { qr[0], qr[4] };
                mma_tf32(s[nt], af, bf);
            }
        }

        const int r0 = i0 + mo + g, r1 = r0 + 8;
        if (j0 == i0) {
#pragma unroll
            for (int nt = 0; nt < 4; nt++) {
                int c0 = j0 + so + nt * 8 + 2 * t4;
                s[nt][0] = (c0     <= r0) ? s[nt][0] * scale : NEGINF;
                s[nt][1] = (c0 + 1 <= r0) ? s[nt][1] * scale : NEGINF;
                s[nt][2] = (c0     <= r1) ? s[nt][2] * scale : NEGINF;
                s[nt][3] = (c0 + 1 <= r1) ? s[nt][3] * scale : NEGINF;
            }
        } else {
#pragma unroll
            for (int nt = 0; nt < 4; nt++) {
                s[nt][0] *= scale; s[nt][1] *= scale;
                s[nt][2] *= scale; s[nt][3] *= scale;
            }
        }

        float mx0 = NEGINF, mx1 = NEGINF;
#pragma unroll
        for (int nt = 0; nt < 4; nt++) {
            mx0 = fmaxf(mx0, fmaxf(s[nt][0], s[nt][1]));
            mx1 = fmaxf(mx1, fmaxf(s[nt][2], s[nt][3]));
        }
        mx0 = fmaxf(mx0, __shfl_xor_sync(0xffffffffu, mx0, 1));
        mx0 = fmaxf(mx0, __shfl_xor_sync(0xffffffffu, mx0, 2));
        mx1 = fmaxf(mx1, __shfl_xor_sync(0xffffffffu, mx1, 1));
        mx1 = fmaxf(mx1, __shfl_xor_sync(0xffffffffu, mx1, 2));
        if (t4 == 0) {
            sRM[wn * 64 + mo + g]     = mx0;
            sRM[wn * 64 + mo + g + 8] = mx1;
        }
        __syncthreads();

        const float mo0 = sM[mo + g], mo1 = sM[mo + g + 8];
        const float mn0 = fmaxf(mo0, fmaxf(mx0, sRM[(wn ^ 1) * 64 + mo + g]));
        const float mn1 = fmaxf(mo1, fmaxf(mx1, sRM[(wn ^ 1) * 64 + mo + g + 8]));
        const float al0 = __expf(mo0 - mn0), al1 = __expf(mo1 - mn1);

        float su0 = 0.f, su1 = 0.f;
#pragma unroll
        for (int nt = 0; nt < 4; nt++) {
            float p0 = __expf(s[nt][0] - mn0), p1 = __expf(s[nt][1] - mn0);
            float p2 = __expf(s[nt][2] - mn1), p3 = __expf(s[nt][3] - mn1);
            su0 += p0 + p1; su1 += p2 + p3;
            uint32_t* pr = sP + (mo + g) * PST2 + so + nt * 8 + 2 * t4;
            pr[0] = f2tf32(p0); pr[1] = f2tf32(p1);
            pr[8 * PST2] = f2tf32(p2); pr[8 * PST2 + 1] = f2tf32(p3);
        }
        su0 += __shfl_xor_sync(0xffffffffu, su0, 1);
        su0 += __shfl_xor_sync(0xffffffffu, su0, 2);
        su1 += __shfl_xor_sync(0xffffffffu, su1, 1);
        su1 += __shfl_xor_sync(0xffffffffu, su1, 2);
        if (t4 == 0) {
            sRS[wn * 64 + mo + g]     = su0;
            sRS[wn * 64 + mo + g + 8] = su1;
        }
        __syncthreads();

        if (wn == 0 && t4 == 0) {
            sL[mo + g]     = sL[mo + g]     * al0 + su0 + sRS[64 + mo + g];
            sM[mo + g]     = mn0;
            sL[mo + g + 8] = sL[mo + g + 8] * al1 + su1 + sRS[64 + mo + g + 8];
            sM[mo + g + 8] = mn1;
        }

#pragma unroll
        for (int nt = 0; nt < 8; nt++) {
            o[nt][0] *= al0; o[nt][1] *= al0;
            o[nt][2] *= al1; o[nt][3] *= al1;
        }
#pragma unroll
        for (int ks = 0; ks < 8; ks++) {
            const int kk = ks * 8;
            const uint32_t* pr = sP + (mo + g) * PST2 + kk + t4;
            uint32_t af[4] = { pr[0], pr[8 * PST2], pr[4], pr[8 * PST2 + 4] };
#pragma unroll
            for (int nt = 0; nt < 8; nt++) {
                int vc = ho + nt * 8 + g;
                uint32_t bf[2] = { sV[(kk + t4) * VSTR + vc], sV[(kk + t4 + 4) * VSTR + vc] };
                mma_tf32(o[nt], af, bf);
            }
        }
        __syncthreads();

        if (t + 1 < ntiles) {
            const float* q0 = qg + (size_t)(j0 + 64) * H_DIM;
            const float* v0 = vg + (size_t)(j0 + 64) * H_DIM;
#pragma unroll
            for (int tt = 0; tt < 8; tt++) {
                int id = tid + tt * 256;
                int r = id >> 5, gr = id & 31;
                cp_async16(smem_u32(sQ + r * KSTR + gr * 4), q0 + (size_t)r * H_DIM + gr * 4);
                cp_async16(smem_u32(sV + r * VSTR + gr * 4), v0 + (size_t)r * H_DIM + gr * 4);
            }
            cp_commit();
            cp_wait0();
            __syncthreads();
        }
    }

    const size_t p = ((size_t)(b * 64 + m)) * 8 + c;
    float* po = g_po + p * 8192;
#pragma unroll
    for (int nt = 0; nt < 8; nt++) {
        int cc = ho + nt * 8 + 2 * t4;
        *reinterpret_cast<float2*>(&po[(mo + g) * 128 + cc])     = make_float2(o[nt][0], o[nt][1]);
        *reinterpret_cast<float2*>(&po[(mo + g + 8) * 128 + cc]) = make_float2(o[nt][2], o[nt][3]);
    }
    __syncthreads();
    if (tid < 64) g_ml[p * 64 + tid] = make_float2(sM[tid], sL[tid]);
}

// ============================================================================
// Kernel 3: merge split-K partials (unchanged).
// ============================================================================
__global__ void __launch_bounds__(256) merge_kernel(float* __restrict__ out)
{
    const int m = blockIdx.x, b = blockIdx.y;
    const int nch = (m >> 3) + 1;
    const int r  = threadIdx.x >> 2;
    const int cg = threadIdx.x & 3;
    const size_t pb = ((size_t)(b * 64 + m)) * 8;

    float mst = __int_as_float(0xff800000);
    float wts[8];
#pragma unroll 1
    for (int c = 0; c < nch; c++)
        mst = fmaxf(mst, g_ml[(pb + c) * 64 + r].x);
    float den = 0.f;
#pragma unroll 1
    for (int c = 0; c < nch; c++) {
        float2 ml = g_ml[(pb + c) * 64 + r];
        wts[c] = __expf(ml.x - mst);
        den += wts[c] * ml.y;
    }
    const float inv = 1.f / den;

    float* orow = out + ((size_t)b * T_DIM + m * 64 + r) * H_DIM + cg * 32;
#pragma unroll
    for (int q = 0; q < 8; q++) {
        float4 acc = make_float4(0.f, 0.f, 0.f, 0.f);
#pragma unroll 1
        for (int c = 0; c < nch; c++) {
            const float* po = g_po + (pb + c) * 8192 + (size_t)r * 128 + cg * 32 + q * 4;
            float4 v = *reinterpret_cast<const float4*>(po);
            acc.x += wts[c] * v.x; acc.y += wts[c] * v.y;
            acc.z += wts[c] * v.z; acc.w += wts[c] * v.w;
        }
        acc.x *= inv; acc.y *= inv; acc.z *= inv; acc.w *= inv;
        *reinterpret_cast<float4*>(orow + q * 4) = acc;
    }
}

extern "C" void kernel_launch(void* const* d_in, const int* in_sizes, int n_in,
                              void* d_out, int out_size)
{
    const float* idx = (const float*)d_in[0];
    const float* Wq  = (const float*)d_in[1];
    const float* Wk  = (const float*)d_in[2];
    const float* Wv  = (const float*)d_in[3];
    float* out = (float*)d_out;
    (void)in_sizes; (void)n_in; (void)out_size;

    cudaFuncSetAttribute(proj_kernel, cudaFuncAttributeMaxDynamicSharedMemorySize, PJ_BYTES);
    cudaFuncSetAttribute(attn_kernel, cudaFuncAttributeMaxDynamicSharedMemorySize, ATT_BYTES);

    cvtw_kernel<<<768, 256>>>(Wq, Wk, Wv);
    proj_kernel<<<dim3(3, (B_DIM * T_DIM) / 64), 256, PJ_BYTES>>>(idx);
    attn_kernel<<<dim3(8, 64, B_DIM), 256, ATT_BYTES>>>();
    merge_kernel<<<dim3(64, B_DIM), 256>>>(out);
}

// round 10
// speedup vs baseline: 1.6416x; 1.1777x over previous
#include <cuda_runtime.h>
#include <cstdint>

#define B_DIM 4
#define T_DIM 4096
#define C_DIM 2048
#define H_DIM 128

__device__ float g_q[(size_t)B_DIM * T_DIM * H_DIM];
__device__ float g_k[(size_t)B_DIM * T_DIM * H_DIM];
__device__ float g_v[(size_t)B_DIM * T_DIM * H_DIM];
__device__ float g_w[3 * H_DIM * C_DIM];       // W pre-rounded to tf32
// split-K partials: 4 batches x 64 row-blocks x 8 chunks
__device__ float  g_po[(size_t)2048 * 8192];   // O partials [64][128]
__device__ float2 g_ml[(size_t)2048 * 64];     // per-row (m, l)

__device__ __forceinline__ uint32_t f2tf32(float f) {
    uint32_t r;
    asm("cvt.rna.tf32.f32 %0, %1;" : "=r"(r) : "f"(f));
    return r;
}
__device__ __forceinline__ float tf32r(float f) { return __uint_as_float(f2tf32(f)); }

__device__ __forceinline__ void mma_tf32(float* c, const uint32_t* a, const uint32_t* b) {
    asm volatile(
        "mma.sync.aligned.m16n8k8.row.col.f32.tf32.tf32.f32 "
        "{%0,%1,%2,%3}, {%4,%5,%6,%7}, {%8,%9}, {%0,%1,%2,%3};\n"
        : "+f"(c[0]), "+f"(c[1]), "+f"(c[2]), "+f"(c[3])
        : "r"(a[0]), "r"(a[1]), "r"(a[2]), "r"(a[3]), "r"(b[0]), "r"(b[1]));
}

__device__ __forceinline__ uint32_t smem_u32(const void* p) {
    return (uint32_t)__cvta_generic_to_shared(p);
}
__device__ __forceinline__ void cp_async16(uint32_t dst, const void* src) {
    asm volatile("cp.async.cg.shared.global [%0], [%1], 16;\n" :: "r"(dst), "l"(src) : "memory");
}
__device__ __forceinline__ void cp_commit() { asm volatile("cp.async.commit_group;\n" ::: "memory"); }
__device__ __forceinline__ void cp_wait0()  { asm volatile("cp.async.wait_group 0;\n" ::: "memory"); }
__device__ __forceinline__ void cp_wait2()  { asm volatile("cp.async.wait_group 2;\n" ::: "memory"); }

// swizzled word index in a row-major [rows x 32-word] tile (16B granules)
__device__ __forceinline__ int swz(int r, int w) {
    return r * 32 + (((w >> 2) ^ (r & 7)) << 2) + (w & 3);
}

// ============================================================================
// Kernel 0: W -> tf32-rounded copy (3 x [128,2048]).
// ============================================================================
__global__ void cvtw_kernel(const float* __restrict__ Wq,
                            const float* __restrict__ Wk,
                            const float* __restrict__ Wv)
{
    const int per = H_DIM * C_DIM;
    int i = (blockIdx.x * 256 + threadIdx.x) * 4;
    const float* src = (i < per) ? Wq : (i < 2 * per ? Wk : Wv);
    float4 v = *reinterpret_cast<const float4*>(&src[i % per]);
    float4 r = { tf32r(v.x), tf32r(v.y), tf32r(v.z), tf32r(v.w) };
    *reinterpret_cast<float4*>(&g_w[i]) = r;
}

// ============================================================================
// Kernel 1: projections, 3-stage cp.async pipeline, 64x128 tile, 2 CTAs/SM.
// A = raw fp32 idx (HMMA truncates mantissa in HW — no cvt in mainloop).
// B = g_w (pre-rounded rna). Outputs rounded to tf32 for the attn kernels.
// ============================================================================
#define PJ_STAGE_W (192 * 32)            // 64 A-rows + 128 B-rows, 32 words each
#define PJ_BYTES   (3 * PJ_STAGE_W * 4)  // 73728 B

__global__ void __launch_bounds__(256, 2) proj_kernel(const float* __restrict__ idx)
{
    extern __shared__ uint32_t ps[];

    const int tid  = threadIdx.x;
    const int warp = tid >> 5, lane = tid & 31;
    const int g = lane >> 2, t4 = lane & 3;
    const int wm = warp >> 2, wn = warp & 3;     // 2 x 4 warp grid
    const int mo = wm * 32, no = wn * 32;        // warp tile 32 x 32
    const int row0 = blockIdx.y * 64;
    const int wsel = blockIdx.x;

    const float* A  = idx + (size_t)row0 * C_DIM;
    const float* Bw = g_w + (size_t)wsel * (H_DIM * C_DIM);
    float* out = (wsel == 0) ? g_q : (wsel == 1 ? g_k : g_v);

    auto issue = [&](int chunk) {
        const int kb = chunk * 32;
        uint32_t* st = ps + (chunk % 3) * PJ_STAGE_W;
#pragma unroll
        for (int t = 0; t < 2; t++) {
            int id = tid + t * 256;
            int r = id >> 3, gr = id & 7;
            cp_async16(smem_u32(st + r * 32 + ((gr ^ (r & 7)) << 2)),
                       A + (size_t)r * C_DIM + kb + gr * 4);
        }
        uint32_t* stB = st + 64 * 32;
#pragma unroll
        for (int t = 0; t < 4; t++) {
            int id = tid + t * 256;
            int r = id >> 3, gr = id & 7;
            cp_async16(smem_u32(stB + r * 32 + ((gr ^ (r & 7)) << 2)),
                       Bw + (size_t)r * C_DIM + kb + gr * 4);
        }
        cp_commit();
    };

    float acc[2][4][4] = {};

    issue(0); issue(1); issue(2);

    for (int k = 0; k < 64; k++) {
        cp_wait2();
        __syncthreads();
        const uint32_t* bA = ps + (k % 3) * PJ_STAGE_W;
        const uint32_t* bB = bA + 64 * 32;
#pragma unroll
        for (int ks = 0; ks < 4; ks++) {
            const int kk = ks * 8;
            uint32_t af[2][4];
#pragma unroll
            for (int mt = 0; mt < 2; mt++) {
                int r0 = mo + mt * 16 + g;
                af[mt][0] = bA[swz(r0,     kk + t4)];
                af[mt][1] = bA[swz(r0 + 8, kk + t4)];
                af[mt][2] = bA[swz(r0,     kk + t4 + 4)];
                af[mt][3] = bA[swz(r0 + 8, kk + t4 + 4)];
            }
#pragma unroll
            for (int nt = 0; nt < 4; nt++) {
                int nc = no + nt * 8 + g;
                uint32_t bf[2] = { bB[swz(nc, kk + t4)], bB[swz(nc, kk + t4 + 4)] };
                mma_tf32(acc[0][nt], af[0], bf);
                mma_tf32(acc[1][nt], af[1], bf);
            }
        }
        __syncthreads();
        if (k + 3 < 64) issue(k + 3);
        else cp_commit();  // keep group count aligned for cp_wait2
    }

#pragma unroll
    for (int mt = 0; mt < 2; mt++) {
#pragma unroll
        for (int nt = 0; nt < 4; nt++) {
            int r  = row0 + mo + mt * 16 + g;
            int cc = no + nt * 8 + 2 * t4;
            out[(size_t)r * H_DIM + cc]           = tf32r(acc[mt][nt][0]);
            out[(size_t)r * H_DIM + cc + 1]       = tf32r(acc[mt][nt][1]);
            out[(size_t)(r + 8) * H_DIM + cc]     = tf32r(acc[mt][nt][2]);
            out[(size_t)(r + 8) * H_DIM + cc + 1] = tf32r(acc[mt][nt][3]);
        }
    }
}

// ============================================================================
// Kernel 2: split-K flash attention partials (unchanged).
// ============================================================================
#define KSTR 132
#define VSTR 136
#define PST2 68
#define OQ   (64 * KSTR)
#define OV   (OQ + 64 * KSTR)
#define ORM  (OV + 64 * VSTR)
#define ORS  (ORM + 128)
#define OM_  (ORS + 128)
#define OL_  (OM_ + 64)
#define ATT_BYTES ((OL_ + 64) * 4)

__global__ void __launch_bounds__(256, 2) attn_kernel()
{
    extern __shared__ uint32_t sm[];
    uint32_t* sK = sm;
    uint32_t* sQ = sm + OQ;
    uint32_t* sV = sm + OV;
    uint32_t* sP = sQ;  // alias
    float* sRM = (float*)(sm + ORM);
    float* sRS = (float*)(sm + ORS);
    float* sM  = (float*)(sm + OM_);
    float* sL  = (float*)(sm + OL_);

    const int m = 63 - blockIdx.y;  // heavy first
    const int c = blockIdx.x;
    if (c * 8 > m) return;
    const int b = blockIdx.z;
    const int i0 = m * 64;
    const int jstart = c * 512;
    const int ntiles = min(8, m + 1 - c * 8);

    const int tid  = threadIdx.x;
    const int warp = tid >> 5, lane = tid & 31;
    const int g = lane >> 2, t4 = lane & 3;
    const int wm = warp & 3, wn = warp >> 2;
    const int mo = wm * 16, so = wn * 32, ho = wn * 64;
    const float scale = 0.022097086912079608f;
    const float NEGINF = __int_as_float(0xff800000);

    const float* kg = g_k + ((size_t)b * T_DIM + i0) * H_DIM;
    const float* qg = g_q + (size_t)b * T_DIM * H_DIM;
    const float* vg = g_v + (size_t)b * T_DIM * H_DIM;

#pragma unroll
    for (int t = 0; t < 8; t++) {
        int id = tid + t * 256;
        int r = id >> 5, gr = id & 31;
        cp_async16(smem_u32(sK + r * KSTR + gr * 4), kg + (size_t)r * H_DIM + gr * 4);
    }
    {
        const float* q0 = qg + (size_t)jstart * H_DIM;
        const float* v0 = vg + (size_t)jstart * H_DIM;
#pragma unroll
        for (int t = 0; t < 8; t++) {
            int id = tid + t * 256;
            int r = id >> 5, gr = id & 31;
            cp_async16(smem_u32(sQ + r * KSTR + gr * 4), q0 + (size_t)r * H_DIM + gr * 4);
            cp_async16(smem_u32(sV + r * VSTR + gr * 4), v0 + (size_t)r * H_DIM + gr * 4);
        }
    }
    cp_commit();
    if (tid < 64) { sM[tid] = NEGINF; sL[tid] = 0.f; }
    cp_wait0();
    __syncthreads();

    float o[8][4] = {};

    for (int t = 0; t < ntiles; t++) {
        const int j0 = jstart + t * 64;

        float s[4][4] = {};
#pragma unroll
        for (int ks = 0; ks < 16; ks++) {
            const int kk = ks * 8;
            const uint32_t* kr = sK + (mo + g) * KSTR + kk + t4;
            uint32_t af[4] = { kr[0], kr[8 * KSTR], kr[4], kr[8 * KSTR + 4] };
#pragma unroll
            for (int nt = 0; nt < 4; nt++) {
                const uint32_t* qr = sQ + (so + nt * 8 + g) * KSTR + kk + t4;
                uint32_t bf[2] = { qr[0], qr[4] };
                mma_tf32(s[nt], af, bf);
            }
        }

        const int r0 = i0 + mo + g, r1 = r0 + 8;
        if (j0 == i0) {
#pragma unroll
            for (int nt = 0; nt < 4; nt++) {
                int c0 = j0 + so + nt * 8 + 2 * t4;
                s[nt][0] = (c0     <= r0) ? s[nt][0] * scale : NEGINF;
                s[nt][1] = (c0 + 1 <= r0) ? s[nt][1] * scale : NEGINF;
                s[nt][2] = (c0     <= r1) ? s[nt][2] * scale : NEGINF;
                s[nt][3] = (c0 + 1 <= r1) ? s[nt][3] * scale : NEGINF;
            }
        } else {
#pragma unroll
            for (int nt = 0; nt < 4; nt++) {
                s[nt][0] *= scale; s[nt][1] *= scale;
                s[nt][2] *= scale; s[nt][3] *= scale;
            }
        }

        float mx0 = NEGINF, mx1 = NEGINF;
#pragma unroll
        for (int nt = 0; nt < 4; nt++) {
            mx0 = fmaxf(mx0, fmaxf(s[nt][0], s[nt][1]));
            mx1 = fmaxf(mx1, fmaxf(s[nt][2], s[nt][3]));
        }
        mx0 = fmaxf(mx0, __shfl_xor_sync(0xffffffffu, mx0, 1));
        mx0 = fmaxf(mx0, __shfl_xor_sync(0xffffffffu, mx0, 2));
        mx1 = fmaxf(mx1, __shfl_xor_sync(0xffffffffu, mx1, 1));
        mx1 = fmaxf(mx1, __shfl_xor_sync(0xffffffffu, mx1, 2));
        if (t4 == 0) {
            sRM[wn * 64 + mo + g]     = mx0;
            sRM[wn * 64 + mo + g + 8] = mx1;
        }
        __syncthreads();

        const float mo0 = sM[mo + g], mo1 = sM[mo + g + 8];
        const float mn0 = fmaxf(mo0, fmaxf(mx0, sRM[(wn ^ 1) * 64 + mo + g]));
        const float mn1 = fmaxf(mo1, fmaxf(mx1, sRM[(wn ^ 1) * 64 + mo + g + 8]));
        const float al0 = __expf(mo0 - mn0), al1 = __expf(mo1 - mn1);

        float su0 = 0.f, su1 = 0.f;
#pragma unroll
        for (int nt = 0; nt < 4; nt++) {
            float p0 = __expf(s[nt][0] - mn0), p1 = __expf(s[nt][1] - mn0);
            float p2 = __expf(s[nt][2] - mn1), p3 = __expf(s[nt][3] - mn1);
            su0 += p0 + p1; su1 += p2 + p3;
            uint32_t* pr = sP + (mo + g) * PST2 + so + nt * 8 + 2 * t4;
            pr[0] = f2tf32(p0); pr[1] = f2tf32(p1);
            pr[8 * PST2] = f2tf32(p2); pr[8 * PST2 + 1] = f2tf32(p3);
        }
        su0 += __shfl_xor_sync(0xffffffffu, su0, 1);
        su0 += __shfl_xor_sync(0xffffffffu, su0, 2);
        su1 += __shfl_xor_sync(0xffffffffu, su1, 1);
        su1 += __shfl_xor_sync(0xffffffffu, su1, 2);
        if (t4 == 0) {
            sRS[wn * 64 + mo + g]     = su0;
            sRS[wn * 64 + mo + g + 8] = su1;
        }
        __syncthreads();

        if (wn == 0 && t4 == 0) {
            sL[mo + g]     = sL[mo + g]     * al0 + su0 + sRS[64 + mo + g];
            sM[mo + g]     = mn0;
            sL[mo + g + 8] = sL[mo + g + 8] * al1 + su1 + sRS[64 + mo + g + 8];
            sM[mo + g + 8] = mn1;
        }

#pragma unroll
        for (int nt = 0; nt < 8; nt++) {
            o[nt][0] *= al0; o[nt][1] *= al0;
            o[nt][2] *= al1; o[nt][3] *= al1;
        }
#pragma unroll
        for (int ks = 0; ks < 8; ks++) {
            const int kk = ks * 8;
            const uint32_t* pr = sP + (mo + g) * PST2 + kk + t4;
            uint32_t af[4] = { pr[0], pr[8 * PST2], pr[4], pr[8 * PST2 + 4] };
#pragma unroll
            for (int nt = 0; nt < 8; nt++) {
                int vc = ho + nt * 8 + g;
                uint32_t bf[2] = { sV[(kk + t4) * VSTR + vc], sV[(kk + t4 + 4) * VSTR + vc] };
                mma_tf32(o[nt], af, bf);
            }
        }
        __syncthreads();

        if (t + 1 < ntiles) {
            const float* q0 = qg + (size_t)(j0 + 64) * H_DIM;
            const float* v0 = vg + (size_t)(j0 + 64) * H_DIM;
#pragma unroll
            for (int tt = 0; tt < 8; tt++) {
                int id = tid + tt * 256;
                int r = id >> 5, gr = id & 31;
                cp_async16(smem_u32(sQ + r * KSTR + gr * 4), q0 + (size_t)r * H_DIM + gr * 4);
                cp_async16(smem_u32(sV + r * VSTR + gr * 4), v0 + (size_t)r * H_DIM + gr * 4);
            }
            cp_commit();
            cp_wait0();
            __syncthreads();
        }
    }

    const size_t p = ((size_t)(b * 64 + m)) * 8 + c;
    float* po = g_po + p * 8192;
#pragma unroll
    for (int nt = 0; nt < 8; nt++) {
        int cc = ho + nt * 8 + 2 * t4;
        *reinterpret_cast<float2*>(&po[(mo + g) * 128 + cc])     = make_float2(o[nt][0], o[nt][1]);
        *reinterpret_cast<float2*>(&po[(mo + g + 8) * 128 + cc]) = make_float2(o[nt][2], o[nt][3]);
    }
    __syncthreads();
    if (tid < 64) g_ml[p * 64 + tid] = make_float2(sM[tid], sL[tid]);
}

// ============================================================================
// Kernel 3: merge split-K partials. 4x parallelism vs R7: each block does
// 64 rows x 32 cols; grid (256, 4).
// ============================================================================
__global__ void __launch_bounds__(256) merge_kernel(float* __restrict__ out)
{
    const int m  = blockIdx.x >> 2;
    const int cq = (blockIdx.x & 3) * 32;   // column quarter
    const int b  = blockIdx.y;
    const int nch = (m >> 3) + 1;
    const int r  = threadIdx.x >> 2;        // row 0..63
    const int c8 = (threadIdx.x & 3) * 8;   // 8 cols per thread
    const size_t pb = ((size_t)(b * 64 + m)) * 8;

    float mst = __int_as_float(0xff800000);
    float wts[8];
#pragma unroll 1
    for (int c = 0; c < nch; c++)
        mst = fmaxf(mst, g_ml[(pb + c) * 64 + r].x);
    float den = 0.f;
#pragma unroll 1
    for (int c = 0; c < nch; c++) {
        float2 ml = g_ml[(pb + c) * 64 + r];
        wts[c] = __expf(ml.x - mst);
        den += wts[c] * ml.y;
    }
    const float inv = 1.f / den;

    float4 a0 = make_float4(0.f, 0.f, 0.f, 0.f);
    float4 a1 = make_float4(0.f, 0.f, 0.f, 0.f);
#pragma unroll 1
    for (int c = 0; c < nch; c++) {
        const float* po = g_po + (pb + c) * 8192 + (size_t)r * 128 + cq + c8;
        float4 v0 = *reinterpret_cast<const float4*>(po);
        float4 v1 = *reinterpret_cast<const float4*>(po + 4);
        float w = wts[c];
        a0.x += w * v0.x; a0.y += w * v0.y; a0.z += w * v0.z; a0.w += w * v0.w;
        a1.x += w * v1.x; a1.y += w * v1.y; a1.z += w * v1.z; a1.w += w * v1.w;
    }
    a0.x *= inv; a0.y *= inv; a0.z *= inv; a0.w *= inv;
    a1.x *= inv; a1.y *= inv; a1.z *= inv; a1.w *= inv;

    float* orow = out + ((size_t)b * T_DIM + m * 64 + r) * H_DIM + cq + c8;
    *reinterpret_cast<float4*>(orow)     = a0;
    *reinterpret_cast<float4*>(orow + 4) = a1;
}

extern "C" void kernel_launch(void* const* d_in, const int* in_sizes, int n_in,
                              void* d_out, int out_size)
{
    const float* idx = (const float*)d_in[0];
    const float* Wq  = (const float*)d_in[1];
    const float* Wk  = (const float*)d_in[2];
    const float* Wv  = (const float*)d_in[3];
    float* out = (float*)d_out;
    (void)in_sizes; (void)n_in; (void)out_size;

    cudaFuncSetAttribute(proj_kernel, cudaFuncAttributeMaxDynamicSharedMemorySize, PJ_BYTES);
    cudaFuncSetAttribute(attn_kernel, cudaFuncAttributeMaxDynamicSharedMemorySize, ATT_BYTES);

    cvtw_kernel<<<768, 256>>>(Wq, Wk, Wv);
    proj_kernel<<<dim3(3, (B_DIM * T_DIM) / 64), 256, PJ_BYTES>>>(idx);
    attn_kernel<<<dim3(8, 64, B_DIM), 256, ATT_BYTES>>>();
    merge_kernel<<<dim3(256, B_DIM), 256>>>(out);
}

// round 13
// speedup vs baseline: 1.7216x; 1.0488x over previous
#include <cuda_runtime.h>
#include <cstdint>

#define B_DIM 4
#define T_DIM 4096
#define C_DIM 2048
#define H_DIM 128

__device__ float g_q[(size_t)B_DIM * T_DIM * H_DIM];
__device__ float g_k[(size_t)B_DIM * T_DIM * H_DIM];
__device__ float g_v[(size_t)B_DIM * T_DIM * H_DIM];
__device__ float g_w[3 * H_DIM * C_DIM];       // W pre-rounded to tf32
__device__ float  g_po[(size_t)2048 * 8192];   // split-K O partials
__device__ float2 g_ml[(size_t)2048 * 64];     // per-row (m, l)

__device__ __forceinline__ uint32_t f2tf32(float f) {
    uint32_t r;
    asm("cvt.rna.tf32.f32 %0, %1;" : "=r"(r) : "f"(f));
    return r;
}
__device__ __forceinline__ float tf32r(float f) { return __uint_as_float(f2tf32(f)); }

__device__ __forceinline__ void mma_tf32(float* c, const uint32_t* a, const uint32_t* b) {
    asm volatile(
        "mma.sync.aligned.m16n8k8.row.col.f32.tf32.tf32.f32 "
        "{%0,%1,%2,%3}, {%4,%5,%6,%7}, {%8,%9}, {%0,%1,%2,%3};\n"
        : "+f"(c[0]), "+f"(c[1]), "+f"(c[2]), "+f"(c[3])
        : "r"(a[0]), "r"(a[1]), "r"(a[2]), "r"(a[3]), "r"(b[0]), "r"(b[1]));
}

__device__ __forceinline__ uint32_t smem_u32(const void* p) {
    return (uint32_t)__cvta_generic_to_shared(p);
}
__device__ __forceinline__ void cp_async16(uint32_t dst, const void* src) {
    asm volatile("cp.async.cg.shared.global [%0], [%1], 16;\n" :: "r"(dst), "l"(src) : "memory");
}
__device__ __forceinline__ void cp_commit() { asm volatile("cp.async.commit_group;\n" ::: "memory"); }
__device__ __forceinline__ void cp_wait0()  { asm volatile("cp.async.wait_group 0;\n" ::: "memory"); }
__device__ __forceinline__ void cp_wait2()  { asm volatile("cp.async.wait_group 2;\n" ::: "memory"); }

// swizzled word index in a row-major [rows x 32-word] tile (16B granules)
__device__ __forceinline__ int swz(int r, int w) {
    return r * 32 + (((w >> 2) ^ (r & 7)) << 2) + (w & 3);
}

// ============================================================================
// Kernel 0: W -> tf32-rounded copy (3 x [128,2048]).
// ============================================================================
__global__ void cvtw_kernel(const float* __restrict__ Wq,
                            const float* __restrict__ Wk,
                            const float* __restrict__ Wv)
{
    const int per = H_DIM * C_DIM;
    int i = (blockIdx.x * 256 + threadIdx.x) * 4;
    const float* src = (i < per) ? Wq : (i < 2 * per ? Wk : Wv);
    float4 v = *reinterpret_cast<const float4*>(&src[i % per]);
    float4 r = { tf32r(v.x), tf32r(v.y), tf32r(v.z), tf32r(v.w) };
    *reinterpret_cast<float4*>(&g_w[i]) = r;
}

// ============================================================================
// Kernel 1: projections. 64x128 block tile, 128 threads (2x2 warps, warp
// tile 32x64 -> LDS/MMA = 1.5), 3-stage cp.async ring, 3 CTAs/SM.
// A = raw fp32 idx (HMMA truncates in HW), B = g_w (pre-rounded rna).
// ============================================================================
#define PJ_STAGE_W (192 * 32)            // 64 A-rows + 128 B-rows, 32 words each
#define PJ_BYTES   (3 * PJ_STAGE_W * 4)  // 73728 B

__global__ void __launch_bounds__(128, 3) proj_kernel(const float* __restrict__ idx)
{
    extern __shared__ uint32_t ps[];

    const int tid  = threadIdx.x;
    const int warp = tid >> 5, lane = tid & 31;
    const int g = lane >> 2, t4 = lane & 3;
    const int wm = warp >> 1, wn = warp & 1;     // 2 x 2 warp grid
    const int mo = wm * 32, no = wn * 64;        // warp tile 32 x 64
    const int row0 = blockIdx.y * 64;
    const int wsel = blockIdx.x;

    const float* A  = idx + (size_t)row0 * C_DIM;
    const float* Bw = g_w + (size_t)wsel * (H_DIM * C_DIM);
    float* out = (wsel == 0) ? g_q : (wsel == 1 ? g_k : g_v);

    auto issue = [&](int chunk) {
        const int kb = chunk * 32;
        uint32_t* st = ps + (chunk % 3) * PJ_STAGE_W;
#pragma unroll
        for (int t = 0; t < 4; t++) {          // A: 512 granules
            int id = tid + t * 128;
            int r = id >> 3, gr = id & 7;
            cp_async16(smem_u32(st + r * 32 + ((gr ^ (r & 7)) << 2)),
                       A + (size_t)r * C_DIM + kb + gr * 4);
        }
        uint32_t* stB = st + 64 * 32;
#pragma unroll
        for (int t = 0; t < 8; t++) {          // B: 1024 granules
            int id = tid + t * 128;
            int r = id >> 3, gr = id & 7;
            cp_async16(smem_u32(stB + r * 32 + ((gr ^ (r & 7)) << 2)),
                       Bw + (size_t)r * C_DIM + kb + gr * 4);
        }
        cp_commit();
    };

    float acc[2][8][4] = {};

    issue(0); issue(1); issue(2);

    for (int k = 0; k < 64; k++) {
        cp_wait2();
        __syncthreads();
        const uint32_t* bA = ps + (k % 3) * PJ_STAGE_W;
        const uint32_t* bB = bA + 64 * 32;
#pragma unroll
        for (int ks = 0; ks < 4; ks++) {
            const int kk = ks * 8;
            uint32_t af[2][4];
#pragma unroll
            for (int mt = 0; mt < 2; mt++) {
                int r0 = mo + mt * 16 + g;
                af[mt][0] = bA[swz(r0,     kk + t4)];
                af[mt][1] = bA[swz(r0 + 8, kk + t4)];
                af[mt][2] = bA[swz(r0,     kk + t4 + 4)];
                af[mt][3] = bA[swz(r0 + 8, kk + t4 + 4)];
            }
#pragma unroll
            for (int nt = 0; nt < 8; nt++) {
                int nc = no + nt * 8 + g;
                uint32_t bf[2] = { bB[swz(nc, kk + t4)], bB[swz(nc, kk + t4 + 4)] };
                mma_tf32(acc[0][nt], af[0], bf);
                mma_tf32(acc[1][nt], af[1], bf);
            }
        }
        __syncthreads();
        if (k + 3 < 64) issue(k + 3);
        else cp_commit();  // keep group count aligned for cp_wait2
    }

#pragma unroll
    for (int mt = 0; mt < 2; mt++) {
#pragma unroll
        for (int nt = 0; nt < 8; nt++) {
            int r  = row0 + mo + mt * 16 + g;
            int cc = no + nt * 8 + 2 * t4;
            out[(size_t)r * H_DIM + cc]           = tf32r(acc[mt][nt][0]);
            out[(size_t)r * H_DIM + cc + 1]       = tf32r(acc[mt][nt][1]);
            out[(size_t)(r + 8) * H_DIM + cc]     = tf32r(acc[mt][nt][2]);
            out[(size_t)(r + 8) * H_DIM + cc + 1] = tf32r(acc[mt][nt][3]);
        }
    }
}

// ============================================================================
// Kernel 2: split-K flash attention partials (unchanged from R10).
// ============================================================================
#define KSTR 132
#define VSTR 136
#define PST2 68
#define OQ   (64 * KSTR)
#define OV   (OQ + 64 * KSTR)
#define ORM  (OV + 64 * VSTR)
#define ORS  (ORM + 128)
#define OM_  (ORS + 128)
#define OL_  (OM_ + 64)
#define ATT_BYTES ((OL_ + 64) * 4)

__global__ void __launch_bounds__(256, 2) attn_kernel()
{
    extern __shared__ uint32_t sm[];
    uint32_t* sK = sm;
    uint32_t* sQ = sm + OQ;
    uint32_t* sV = sm + OV;
    uint32_t* sP = sQ;  // alias
    float* sRM = (float*)(sm + ORM);
    float* sRS = (float*)(sm + ORS);
    float* sM  = (float*)(sm + OM_);
    float* sL  = (float*)(sm + OL_);

    const int m = 63 - blockIdx.y;  // heavy first
    const int c = blockIdx.x;
    if (c * 8 > m) return;
    const int b = blockIdx.z;
    const int i0 = m * 64;
    const int jstart = c * 512;
    const int ntiles = min(8, m + 1 - c * 8);

    const int tid  = threadIdx.x;
    const int warp = tid >> 5, lane = tid & 31;
    const int g = lane >> 2, t4 = lane & 3;
    const int wm = warp & 3, wn = warp >> 2;
    const int mo = wm * 16, so = wn * 32, ho = wn * 64;
    const float scale = 0.022097086912079608f;
    const float NEGINF = __int_as_float(0xff800000);

    const float* kg = g_k + ((size_t)b * T_DIM + i0) * H_DIM;
    const float* qg = g_q + (size_t)b * T_DIM * H_DIM;
    const float* vg = g_v + (size_t)b * T_DIM * H_DIM;

#pragma unroll
    for (int t = 0; t < 8; t++) {
        int id = tid + t * 256;
        int r = id >> 5, gr = id & 31;
        cp_async16(smem_u32(sK + r * KSTR + gr * 4), kg + (size_t)r * H_DIM + gr * 4);
    }
    {
        const float* q0 = qg + (size_t)jstart * H_DIM;
        const float* v0 = vg + (size_t)jstart * H_DIM;
#pragma unroll
        for (int t = 0; t < 8; t++) {
            int id = tid + t * 256;
            int r = id >> 5, gr = id & 31;
            cp_async16(smem_u32(sQ + r * KSTR + gr * 4), q0 + (size_t)r * H_DIM + gr * 4);
            cp_async16(smem_u32(sV + r * VSTR + gr * 4), v0 + (size_t)r * H_DIM + gr * 4);
        }
    }
    cp_commit();
    if (tid < 64) { sM[tid] = NEGINF; sL[tid] = 0.f; }
    cp_wait0();
    __syncthreads();

    float o[8][4] = {};

    for (int t = 0; t < ntiles; t++) {
        const int j0 = jstart + t * 64;

        float s[4][4] = {};
#pragma unroll
        for (int ks = 0; ks < 16; ks++) {
            const int kk = ks * 8;
            const uint32_t* kr = sK + (mo + g) * KSTR + kk + t4;
            uint32_t af[4] = { kr[0], kr[8 * KSTR], kr[4], kr[8 * KSTR + 4] };
#pragma unroll
            for (int nt = 0; nt < 4; nt++) {
                const uint32_t* qr = sQ + (so + nt * 8 + g) * KSTR + kk + t4;
                uint32_t bf[2] = { qr[0], qr[4] };
                mma_tf32(s[nt], af, bf);
            }
        }

        const int r0 = i0 + mo + g, r1 = r0 + 8;
        if (j0 == i0) {
#pragma unroll
            for (int nt = 0; nt < 4; nt++) {
                int c0 = j0 + so + nt * 8 + 2 * t4;
                s[nt][0] = (c0     <= r0) ? s[nt][0] * scale : NEGINF;
                s[nt][1] = (c0 + 1 <= r0) ? s[nt][1] * scale : NEGINF;
                s[nt][2] = (c0     <= r1) ? s[nt][2] * scale : NEGINF;
                s[nt][3] = (c0 + 1 <= r1) ? s[nt][3] * scale : NEGINF;
            }
        } else {
#pragma unroll
            for (int nt = 0; nt < 4; nt++) {
                s[nt][0] *= scale; s[nt][1] *= scale;
                s[nt][2] *= scale; s[nt][3] *= scale;
            }
        }

        float mx0 = NEGINF, mx1 = NEGINF;
#pragma unroll
        for (int nt = 0; nt < 4; nt++) {
            mx0 = fmaxf(mx0, fmaxf(s[nt][0], s[nt][1]));
            mx1 = fmaxf(mx1, fmaxf(s[nt][2], s[nt][3]));
        }
        mx0 = fmaxf(mx0, __shfl_xor_sync(0xffffffffu, mx0, 1));
        mx0 = fmaxf(mx0, __shfl_xor_sync(0xffffffffu, mx0, 2));
        mx1 = fmaxf(mx1, __shfl_xor_sync(0xffffffffu, mx1, 1));
        mx1 = fmaxf(mx1, __shfl_xor_sync(0xffffffffu, mx1, 2));
        if (t4 == 0) {
            sRM[wn * 64 + mo + g]     = mx0;
            sRM[wn * 64 + mo + g + 8] = mx1;
        }
        __syncthreads();

        const float mo0 = sM[mo + g], mo1 = sM[mo + g + 8];
        const float mn0 = fmaxf(mo0, fmaxf(mx0, sRM[(wn ^ 1) * 64 + mo + g]));
        const float mn1 = fmaxf(mo1, fmaxf(mx1, sRM[(wn ^ 1) * 64 + mo + g + 8]));
        const float al0 = __expf(mo0 - mn0), al1 = __expf(mo1 - mn1);

        float su0 = 0.f, su1 = 0.f;
#pragma unroll
        for (int nt = 0; nt < 4; nt++) {
            float p0 = __expf(s[nt][0] - mn0), p1 = __expf(s[nt][1] - mn0);
            float p2 = __expf(s[nt][2] - mn1), p3 = __expf(s[nt][3] - mn1);
            su0 += p0 + p1; su1 += p2 + p3;
            uint32_t* pr = sP + (mo + g) * PST2 + so + nt * 8 + 2 * t4;
            pr[0] = f2tf32(p0); pr[1] = f2tf32(p1);
            pr[8 * PST2] = f2tf32(p2); pr[8 * PST2 + 1] = f2tf32(p3);
        }
        su0 += __shfl_xor_sync(0xffffffffu, su0, 1);
        su0 += __shfl_xor_sync(0xffffffffu, su0, 2);
        su1 += __shfl_xor_sync(0xffffffffu, su1, 1);
        su1 += __shfl_xor_sync(0xffffffffu, su1, 2);
        if (t4 == 0) {
            sRS[wn * 64 + mo + g]     = su0;
            sRS[wn * 64 + mo + g + 8] = su1;
        }
        __syncthreads();

        if (wn == 0 && t4 == 0) {
            sL[mo + g]     = sL[mo + g]     * al0 + su0 + sRS[64 + mo + g];
            sM[mo + g]     = mn0;
            sL[mo + g + 8] = sL[mo + g + 8] * al1 + su1 + sRS[64 + mo + g + 8];
            sM[mo + g + 8] = mn1;
        }

#pragma unroll
        for (int nt = 0; nt < 8; nt++) {
            o[nt][0] *= al0; o[nt][1] *= al0;
            o[nt][2] *= al1; o[nt][3] *= al1;
        }
#pragma unroll
        for (int ks = 0; ks < 8; ks++) {
            const int kk = ks * 8;
            const uint32_t* pr = sP + (mo + g) * PST2 + kk + t4;
            uint32_t af[4] = { pr[0], pr[8 * PST2], pr[4], pr[8 * PST2 + 4] };
#pragma unroll
            for (int nt = 0; nt < 8; nt++) {
                int vc = ho + nt * 8 + g;
                uint32_t bf[2] = { sV[(kk + t4) * VSTR + vc], sV[(kk + t4 + 4) * VSTR + vc] };
                mma_tf32(o[nt], af, bf);
            }
        }
        __syncthreads();

        if (t + 1 < ntiles) {
            const float* q0 = qg + (size_t)(j0 + 64) * H_DIM;
            const float* v0 = vg + (size_t)(j0 + 64) * H_DIM;
#pragma unroll
            for (int tt = 0; tt < 8; tt++) {
                int id = tid + tt * 256;
                int r = id >> 5, gr = id & 31;
                cp_async16(smem_u32(sQ + r * KSTR + gr * 4), q0 + (size_t)r * H_DIM + gr * 4);
                cp_async16(smem_u32(sV + r * VSTR + gr * 4), v0 + (size_t)r * H_DIM + gr * 4);
            }
            cp_commit();
            cp_wait0();
            __syncthreads();
        }
    }

    const size_t p = ((size_t)(b * 64 + m)) * 8 + c;
    float* po = g_po + p * 8192;
#pragma unroll
    for (int nt = 0; nt < 8; nt++) {
        int cc = ho + nt * 8 + 2 * t4;
        *reinterpret_cast<float2*>(&po[(mo + g) * 128 + cc])     = make_float2(o[nt][0], o[nt][1]);
        *reinterpret_cast<float2*>(&po[(mo + g + 8) * 128 + cc]) = make_float2(o[nt][2], o[nt][3]);
    }
    __syncthreads();
    if (tid < 64) g_ml[p * 64 + tid] = make_float2(sM[tid], sL[tid]);
}

// ============================================================================
// Kernel 3: merge split-K partials (unchanged from R10).
// ============================================================================
__global__ void __launch_bounds__(256) merge_kernel(float* __restrict__ out)
{
    const int m  = blockIdx.x >> 2;
    const int cq = (blockIdx.x & 3) * 32;
    const int b  = blockIdx.y;
    const int nch = (m >> 3) + 1;
    const int r  = threadIdx.x >> 2;
    const int c8 = (threadIdx.x & 3) * 8;
    const size_t pb = ((size_t)(b * 64 + m)) * 8;

    float mst = __int_as_float(0xff800000);
    float wts[8];
#pragma unroll 1
    for (int c = 0; c < nch; c++)
        mst = fmaxf(mst, g_ml[(pb + c) * 64 + r].x);
    float den = 0.f;
#pragma unroll 1
    for (int c = 0; c < nch; c++) {
        float2 ml = g_ml[(pb + c) * 64 + r];
        wts[c] = __expf(ml.x - mst);
        den += wts[c] * ml.y;
    }
    const float inv = 1.f / den;

    float4 a0 = make_float4(0.f, 0.f, 0.f, 0.f);
    float4 a1 = make_float4(0.f, 0.f, 0.f, 0.f);
#pragma unroll 1
    for (int c = 0; c < nch; c++) {
        const float* po = g_po + (pb + c) * 8192 + (size_t)r * 128 + cq + c8;
        float4 v0 = *reinterpret_cast<const float4*>(po);
        float4 v1 = *reinterpret_cast<const float4*>(po + 4);
        float w = wts[c];
        a0.x += w * v0.x; a0.y += w * v0.y; a0.z += w * v0.z; a0.w += w * v0.w;
        a1.x += w * v1.x; a1.y += w * v1.y; a1.z += w * v1.z; a1.w += w * v1.w;
    }
    a0.x *= inv; a0.y *= inv; a0.z *= inv; a0.w *= inv;
    a1.x *= inv; a1.y *= inv; a1.z *= inv; a1.w *= inv;

    float* orow = out + ((size_t)b * T_DIM + m * 64 + r) * H_DIM + cq + c8;
    *reinterpret_cast<float4*>(orow)     = a0;
    *reinterpret_cast<float4*>(orow + 4) = a1;
}

extern "C" void kernel_launch(void* const* d_in, const int* in_sizes, int n_in,
                              void* d_out, int out_size)
{
    const float* idx = (const float*)d_in[0];
    const float* Wq  = (const float*)d_in[1];
    const float* Wk  = (const float*)d_in[2];
    const float* Wv  = (const float*)d_in[3];
    float* out = (float*)d_out;
    (void)in_sizes; (void)n_in; (void)out_size;

    cudaFuncSetAttribute(proj_kernel, cudaFuncAttributeMaxDynamicSharedMemorySize, PJ_BYTES);
    cudaFuncSetAttribute(attn_kernel, cudaFuncAttributeMaxDynamicSharedMemorySize, ATT_BYTES);

    cvtw_kernel<<<768, 256>>>(Wq, Wk, Wv);
    proj_kernel<<<dim3(3, (B_DIM * T_DIM) / 64), 128, PJ_BYTES>>>(idx);
    attn_kernel<<<dim3(8, 64, B_DIM), 256, ATT_BYTES>>>();
    merge_kernel<<<dim3(256, B_DIM), 256>>>(out);
}

// round 14
// speedup vs baseline: 1.8157x; 1.0546x over previous
#include <cuda_runtime.h>
#include <cstdint>

#define B_DIM 4
#define T_DIM 4096
#define C_DIM 2048
#define H_DIM 128

__device__ float g_q[(size_t)B_DIM * T_DIM * H_DIM];
__device__ float g_k[(size_t)B_DIM * T_DIM * H_DIM];
__device__ float g_v[(size_t)B_DIM * T_DIM * H_DIM];
__device__ float g_w[3 * H_DIM * C_DIM];       // W pre-rounded to tf32
// split-K partials: 4 batches x 32 row-blocks(128) x 8 chunks
__device__ float  g_po[(size_t)1024 * 16384];  // O partials [128][128]
__device__ float2 g_ml[(size_t)1024 * 128];    // per-row (m, l)

__device__ __forceinline__ uint32_t f2tf32(float f) {
    uint32_t r;
    asm("cvt.rna.tf32.f32 %0, %1;" : "=r"(r) : "f"(f));
    return r;
}
__device__ __forceinline__ float tf32r(float f) { return __uint_as_float(f2tf32(f)); }

__device__ __forceinline__ void mma_tf32(float* c, const uint32_t* a, const uint32_t* b) {
    asm volatile(
        "mma.sync.aligned.m16n8k8.row.col.f32.tf32.tf32.f32 "
        "{%0,%1,%2,%3}, {%4,%5,%6,%7}, {%8,%9}, {%0,%1,%2,%3};\n"
        : "+f"(c[0]), "+f"(c[1]), "+f"(c[2]), "+f"(c[3])
        : "r"(a[0]), "r"(a[1]), "r"(a[2]), "r"(a[3]), "r"(b[0]), "r"(b[1]));
}

__device__ __forceinline__ uint32_t smem_u32(const void* p) {
    return (uint32_t)__cvta_generic_to_shared(p);
}
__device__ __forceinline__ void cp_async16(uint32_t dst, const void* src) {
    asm volatile("cp.async.cg.shared.global [%0], [%1], 16;\n" :: "r"(dst), "l"(src) : "memory");
}
__device__ __forceinline__ void cp_commit() { asm volatile("cp.async.commit_group;\n" ::: "memory"); }
__device__ __forceinline__ void cp_wait1()  { asm volatile("cp.async.wait_group 1;\n" ::: "memory"); }
__device__ __forceinline__ void cp_wait2()  { asm volatile("cp.async.wait_group 2;\n" ::: "memory"); }
__device__ __forceinline__ void cp_wait0()  { asm volatile("cp.async.wait_group 0;\n" ::: "memory"); }

// swizzled word index in a row-major [rows x 32-word] tile (16B granules)
__device__ __forceinline__ int swz(int r, int w) {
    return r * 32 + (((w >> 2) ^ (r & 7)) << 2) + (w & 3);
}

// ============================================================================
// Kernel 0: W -> tf32-rounded copy (3 x [128,2048]).
// ============================================================================
__global__ void cvtw_kernel(const float* __restrict__ Wq,
                            const float* __restrict__ Wk,
                            const float* __restrict__ Wv)
{
    const int per = H_DIM * C_DIM;
    int i = (blockIdx.x * 256 + threadIdx.x) * 4;
    const float* src = (i < per) ? Wq : (i < 2 * per ? Wk : Wv);
    float4 v = *reinterpret_cast<const float4*>(&src[i % per]);
    float4 r = { tf32r(v.x), tf32r(v.y), tf32r(v.z), tf32r(v.w) };
    *reinterpret_cast<float4*>(&g_w[i]) = r;
}

// ============================================================================
// Kernel 1: projections (unchanged from R13).
// ============================================================================
#define PJ_STAGE_W (192 * 32)
#define PJ_BYTES   (3 * PJ_STAGE_W * 4)

__global__ void __launch_bounds__(128, 3) proj_kernel(const float* __restrict__ idx)
{
    extern __shared__ uint32_t ps[];

    const int tid  = threadIdx.x;
    const int warp = tid >> 5, lane = tid & 31;
    const int g = lane >> 2, t4 = lane & 3;
    const int wm = warp >> 1, wn = warp & 1;
    const int mo = wm * 32, no = wn * 64;
    const int row0 = blockIdx.y * 64;
    const int wsel = blockIdx.x;

    const float* A  = idx + (size_t)row0 * C_DIM;
    const float* Bw = g_w + (size_t)wsel * (H_DIM * C_DIM);
    float* out = (wsel == 0) ? g_q : (wsel == 1 ? g_k : g_v);

    auto issue = [&](int chunk) {
        const int kb = chunk * 32;
        uint32_t* st = ps + (chunk % 3) * PJ_STAGE_W;
#pragma unroll
        for (int t = 0; t < 4; t++) {
            int id = tid + t * 128;
            int r = id >> 3, gr = id & 7;
            cp_async16(smem_u32(st + r * 32 + ((gr ^ (r & 7)) << 2)),
                       A + (size_t)r * C_DIM + kb + gr * 4);
        }
        uint32_t* stB = st + 64 * 32;
#pragma unroll
        for (int t = 0; t < 8; t++) {
            int id = tid + t * 128;
            int r = id >> 3, gr = id & 7;
            cp_async16(smem_u32(stB + r * 32 + ((gr ^ (r & 7)) << 2)),
                       Bw + (size_t)r * C_DIM + kb + gr * 4);
        }
        cp_commit();
    };

    float acc[2][8][4] = {};

    issue(0); issue(1); issue(2);

    for (int k = 0; k < 64; k++) {
        cp_wait2();
        __syncthreads();
        const uint32_t* bA = ps + (k % 3) * PJ_STAGE_W;
        const uint32_t* bB = bA + 64 * 32;
#pragma unroll
        for (int ks = 0; ks < 4; ks++) {
            const int kk = ks * 8;
            uint32_t af[2][4];
#pragma unroll
            for (int mt = 0; mt < 2; mt++) {
                int r0 = mo + mt * 16 + g;
                af[mt][0] = bA[swz(r0,     kk + t4)];
                af[mt][1] = bA[swz(r0 + 8, kk + t4)];
                af[mt][2] = bA[swz(r0,     kk + t4 + 4)];
                af[mt][3] = bA[swz(r0 + 8, kk + t4 + 4)];
            }
#pragma unroll
            for (int nt = 0; nt < 8; nt++) {
                int nc = no + nt * 8 + g;
                uint32_t bf[2] = { bB[swz(nc, kk + t4)], bB[swz(nc, kk + t4 + 4)] };
                mma_tf32(acc[0][nt], af[0], bf);
                mma_tf32(acc[1][nt], af[1], bf);
            }
        }
        __syncthreads();
        if (k + 3 < 64) issue(k + 3);
        else cp_commit();
    }

#pragma unroll
    for (int mt = 0; mt < 2; mt++) {
#pragma unroll
        for (int nt = 0; nt < 8; nt++) {
            int r  = row0 + mo + mt * 16 + g;
            int cc = no + nt * 8 + 2 * t4;
            out[(size_t)r * H_DIM + cc]           = tf32r(acc[mt][nt][0]);
            out[(size_t)r * H_DIM + cc + 1]       = tf32r(acc[mt][nt][1]);
            out[(size_t)(r + 8) * H_DIM + cc]     = tf32r(acc[mt][nt][2]);
            out[(size_t)(r + 8) * H_DIM + cc + 1] = tf32r(acc[mt][nt][3]);
        }
    }
}

// ============================================================================
// Kernel 2: split-K flash attention, BM=128, BN=64, chunk=512 cols.
// 8 warps as 4m x 2n: S warp tile 32x32 (LDS/MMA 2.0), PV 32x64 (1.5).
// Q double-buffered, V single-buffered; cp.async groups staggered so
// Q(t+1) loads under S-mma(t), V(t+1) under S-mma(t+1). 1 CTA/SM.
// ============================================================================
#define KSTR 132
#define VSTR 136
#define PST2 68
#define OQ_   (128 * KSTR)                 // K: 128 rows
#define QBUF  (64 * KSTR)
#define OV_   (OQ_ + 2 * QBUF)             // Q: 2 x 64 rows
#define OP_   (OV_ + 64 * VSTR)            // V: 64 rows
#define ORM_  (OP_ + 128 * PST2)           // P: 128 x 64
#define ORS_  (ORM_ + 256)
#define OM2_  (ORS_ + 256)
#define OL2_  (OM2_ + 128)
#define ATT_BYTES ((OL2_ + 128) * 4)       // 207872 B

__global__ void __launch_bounds__(256, 1) attn_kernel()
{
    extern __shared__ uint32_t sm[];
    uint32_t* sK = sm;
    uint32_t* sQ = sm + OQ_;
    uint32_t* sV = sm + OV_;
    uint32_t* sP = sm + OP_;
    float* sRM = (float*)(sm + ORM_);
    float* sRS = (float*)(sm + ORS_);
    float* sM  = (float*)(sm + OM2_);
    float* sL  = (float*)(sm + OL2_);

    const int m = 31 - blockIdx.y;          // heavy first
    const int c = blockIdx.x;
    if (4 * c > m) return;
    const int b = blockIdx.z;
    const int i0 = m * 128;
    const int jstart = c * 512;
    const int ntiles = min(8, 2 * m + 2 - 8 * c);

    const int tid  = threadIdx.x;
    const int warp = tid >> 5, lane = tid & 31;
    const int g = lane >> 2, t4 = lane & 3;
    const int wm = warp & 3, wn = warp >> 2;
    const int mo = wm * 32;                 // 32 rows per m-warp
    const int so = wn * 32;                 // S col offset
    const int ho = wn * 64;                 // O col offset
    const float scale = 0.022097086912079608f;
    const float NEGINF = __int_as_float(0xff800000);

    const float* kg = g_k + ((size_t)b * T_DIM + i0) * H_DIM;
    const float* qg = g_q + (size_t)b * T_DIM * H_DIM;
    const float* vg = g_v + (size_t)b * T_DIM * H_DIM;

    auto issue_q = [&](int t) {
        const float* q0 = qg + (size_t)(jstart + t * 64) * H_DIM;
        uint32_t* dst = sQ + (t & 1) * QBUF;
#pragma unroll
        for (int i = 0; i < 8; i++) {
            int id = tid + i * 256;
            int r = id >> 5, gr = id & 31;
            cp_async16(smem_u32(dst + r * KSTR + gr * 4), q0 + (size_t)r * H_DIM + gr * 4);
        }
    };
    auto issue_v = [&](int t) {
        const float* v0 = vg + (size_t)(jstart + t * 64) * H_DIM;
#pragma unroll
        for (int i = 0; i < 8; i++) {
            int id = tid + i * 256;
            int r = id >> 5, gr = id & 31;
            cp_async16(smem_u32(sV + r * VSTR + gr * 4), v0 + (size_t)r * H_DIM + gr * 4);
        }
    };

    // prologue: group {K, Q0}, group {V0}
#pragma unroll
    for (int i = 0; i < 16; i++) {
        int id = tid + i * 256;
        int r = id >> 5, gr = id & 31;
        cp_async16(smem_u32(sK + r * KSTR + gr * 4), kg + (size_t)r * H_DIM + gr * 4);
    }
    issue_q(0);
    cp_commit();
    issue_v(0);
    cp_commit();
    if (tid < 128) { sM[tid] = NEGINF; sL[tid] = 0.f; }

    float o[2][8][4] = {};

    for (int t = 0; t < ntiles; t++) {
        const int j0 = jstart + t * 64;

        // group A_t: next Q (possibly empty)
        if (t + 1 < ntiles) issue_q(t + 1);
        cp_commit();
        cp_wait2();                 // K + Q(t) landed
        __syncthreads();

        // ---- S = K . Q^T, warp tile 32 x 32, registers
        const uint32_t* qb = sQ + (t & 1) * QBUF;
        float s[2][4][4] = {};
#pragma unroll
        for (int ks = 0; ks < 16; ks++) {
            const int kk = ks * 8;
            uint32_t af[2][4];
#pragma unroll
            for (int mt = 0; mt < 2; mt++) {
                const uint32_t* kr = sK + (mo + mt * 16 + g) * KSTR + kk + t4;
                af[mt][0] = kr[0]; af[mt][1] = kr[8 * KSTR];
                af[mt][2] = kr[4]; af[mt][3] = kr[8 * KSTR + 4];
            }
#pragma unroll
            for (int nt = 0; nt < 4; nt++) {
                const uint32_t* qr = qb + (so + nt * 8 + g) * KSTR + kk + t4;
                uint32_t bf[2] = { qr[0], qr[4] };
                mma_tf32(s[0][nt], af[0], bf);
                mma_tf32(s[1][nt], af[1], bf);
            }
        }

        // ---- scale (+ mask when tile straddles the diagonal)
        if (j0 + 63 > i0 + mo) {  // any row in this warp's range may mask
#pragma unroll
            for (int mt = 0; mt < 2; mt++) {
                const int r0 = i0 + mo + mt * 16 + g, r1 = r0 + 8;
#pragma unroll
                for (int nt = 0; nt < 4; nt++) {
                    int c0 = j0 + so + nt * 8 + 2 * t4;
                    s[mt][nt][0] = (c0     <= r0) ? s[mt][nt][0] * scale : NEGINF;
                    s[mt][nt][1] = (c0 + 1 <= r0) ? s[mt][nt][1] * scale : NEGINF;
                    s[mt][nt][2] = (c0     <= r1) ? s[mt][nt][2] * scale : NEGINF;
                    s[mt][nt][3] = (c0 + 1 <= r1) ? s[mt][nt][3] * scale : NEGINF;
                }
            }
        } else {
#pragma unroll
            for (int mt = 0; mt < 2; mt++)
#pragma unroll
                for (int nt = 0; nt < 4; nt++) {
                    s[mt][nt][0] *= scale; s[mt][nt][1] *= scale;
                    s[mt][nt][2] *= scale; s[mt][nt][3] *= scale;
                }
        }

        // ---- row maxes (per mt: rows mo+mt*16+g, +8)
        float mx[2][2];
#pragma unroll
        for (int mt = 0; mt < 2; mt++) {
            float m0 = NEGINF, m1 = NEGINF;
#pragma unroll
            for (int nt = 0; nt < 4; nt++) {
                m0 = fmaxf(m0, fmaxf(s[mt][nt][0], s[mt][nt][1]));
                m1 = fmaxf(m1, fmaxf(s[mt][nt][2], s[mt][nt][3]));
            }
            m0 = fmaxf(m0, __shfl_xor_sync(0xffffffffu, m0, 1));
            m0 = fmaxf(m0, __shfl_xor_sync(0xffffffffu, m0, 2));
            m1 = fmaxf(m1, __shfl_xor_sync(0xffffffffu, m1, 1));
            m1 = fmaxf(m1, __shfl_xor_sync(0xffffffffu, m1, 2));
            mx[mt][0] = m0; mx[mt][1] = m1;
            if (t4 == 0) {
                sRM[wn * 128 + mo + mt * 16 + g]     = m0;
                sRM[wn * 128 + mo + mt * 16 + g + 8] = m1;
            }
        }
        __syncthreads();

        float mn[2][2], al[2][2];
#pragma unroll
        for (int mt = 0; mt < 2; mt++) {
            int r0 = mo + mt * 16 + g;
            float mo0 = sM[r0], mo1 = sM[r0 + 8];
            mn[mt][0] = fmaxf(mo0, fmaxf(mx[mt][0], sRM[(wn ^ 1) * 128 + r0]));
            mn[mt][1] = fmaxf(mo1, fmaxf(mx[mt][1], sRM[(wn ^ 1) * 128 + r0 + 8]));
            al[mt][0] = __expf(mo0 - mn[mt][0]);
            al[mt][1] = __expf(mo1 - mn[mt][1]);
        }

        // ---- exp, write P (tf32), partial sums
        float su[2][2] = {};
#pragma unroll
        for (int mt = 0; mt < 2; mt++) {
#pragma unroll
            for (int nt = 0; nt < 4; nt++) {
                float p0 = __expf(s[mt][nt][0] - mn[mt][0]);
                float p1 = __expf(s[mt][nt][1] - mn[mt][0]);
                float p2 = __expf(s[mt][nt][2] - mn[mt][1]);
                float p3 = __expf(s[mt][nt][3] - mn[mt][1]);
                su[mt][0] += p0 + p1; su[mt][1] += p2 + p3;
                uint32_t* pr = sP + (mo + mt * 16 + g) * PST2 + so + nt * 8 + 2 * t4;
                pr[0] = f2tf32(p0); pr[1] = f2tf32(p1);
                pr[8 * PST2] = f2tf32(p2); pr[8 * PST2 + 1] = f2tf32(p3);
            }
            su[mt][0] += __shfl_xor_sync(0xffffffffu, su[mt][0], 1);
            su[mt][0] += __shfl_xor_sync(0xffffffffu, su[mt][0], 2);
            su[mt][1] += __shfl_xor_sync(0xffffffffu, su[mt][1], 1);
            su[mt][1] += __shfl_xor_sync(0xffffffffu, su[mt][1], 2);
            if (t4 == 0) {
                sRS[wn * 128 + mo + mt * 16 + g]     = su[mt][0];
                sRS[wn * 128 + mo + mt * 16 + g + 8] = su[mt][1];
            }
        }
        __syncthreads();

        if (wn == 0 && t4 == 0) {
#pragma unroll
            for (int mt = 0; mt < 2; mt++) {
                int r0 = mo + mt * 16 + g;
                sL[r0]     = sL[r0]     * al[mt][0] + su[mt][0] + sRS[128 + r0];
                sM[r0]     = mn[mt][0];
                sL[r0 + 8] = sL[r0 + 8] * al[mt][1] + su[mt][1] + sRS[128 + r0 + 8];
                sM[r0 + 8] = mn[mt][1];
            }
        }

        // ---- V(t) must be resident before PV
        cp_wait1();
        __syncthreads();

        // ---- rescale O, then O += P . V (warp tile 32 x 64)
#pragma unroll
        for (int mt = 0; mt < 2; mt++)
#pragma unroll
            for (int nt = 0; nt < 8; nt++) {
                o[mt][nt][0] *= al[mt][0]; o[mt][nt][1] *= al[mt][0];
                o[mt][nt][2] *= al[mt][1]; o[mt][nt][3] *= al[mt][1];
            }
#pragma unroll
        for (int ks = 0; ks < 8; ks++) {
            const int kk = ks * 8;
            uint32_t af[2][4];
#pragma unroll
            for (int mt = 0; mt < 2; mt++) {
                const uint32_t* pr = sP + (mo + mt * 16 + g) * PST2 + kk + t4;
                af[mt][0] = pr[0]; af[mt][1] = pr[8 * PST2];
                af[mt][2] = pr[4]; af[mt][3] = pr[8 * PST2 + 4];
            }
#pragma unroll
            for (int nt = 0; nt < 8; nt++) {
                int vc = ho + nt * 8 + g;
                uint32_t bf[2] = { sV[(kk + t4) * VSTR + vc], sV[(kk + t4 + 4) * VSTR + vc] };
                mma_tf32(o[0][nt], af[0], bf);
                mma_tf32(o[1][nt], af[1], bf);
            }
        }
        __syncthreads();            // V consumed by all warps

        // group B_t: next V (possibly empty)
        if (t + 1 < ntiles) issue_v(t + 1);
        cp_commit();
    }

    // ---- write partials (unnormalized O + per-row m,l)
    const size_t p = ((size_t)(b * 32 + m)) * 8 + c;
    float* po = g_po + p * 16384;
#pragma unroll
    for (int mt = 0; mt < 2; mt++) {
#pragma unroll
        for (int nt = 0; nt < 8; nt++) {
            int row = mo + mt * 16 + g;
            int cc  = ho + nt * 8 + 2 * t4;
            *reinterpret_cast<float2*>(&po[(size_t)row * 128 + cc])       = make_float2(o[mt][nt][0], o[mt][nt][1]);
            *reinterpret_cast<float2*>(&po[(size_t)(row + 8) * 128 + cc]) = make_float2(o[mt][nt][2], o[mt][nt][3]);
        }
    }
    __syncthreads();
    if (tid < 128) g_ml[p * 128 + tid] = make_float2(sM[tid], sL[tid]);
}

// ============================================================================
// Kernel 3: merge split-K partials (128-row blocks, 8 col-sixteenths).
// ============================================================================
__global__ void __launch_bounds__(256) merge_kernel(float* __restrict__ out)
{
    const int m  = blockIdx.x >> 3;          // 0..31
    const int cq = (blockIdx.x & 7) * 16;    // column sixteenth
    const int b  = blockIdx.y;
    const int nch = (m >> 2) + 1;
    const int r  = threadIdx.x >> 1;         // row 0..127
    const int c8 = (threadIdx.x & 1) * 8;    // 8 cols per thread
    const size_t pb = ((size_t)(b * 32 + m)) * 8;

    float mst = __int_as_float(0xff800000);
    float wts[8];
#pragma unroll 1
    for (int c = 0; c < nch; c++)
        mst = fmaxf(mst, g_ml[(pb + c) * 128 + r].x);
    float den = 0.f;
#pragma unroll 1
    for (int c = 0; c < nch; c++) {
        float2 ml = g_ml[(pb + c) * 128 + r];
        wts[c] = __expf(ml.x - mst);
        den += wts[c] * ml.y;
    }
    const float inv = 1.f / den;

    float4 a0 = make_float4(0.f, 0.f, 0.f, 0.f);
    float4 a1 = make_float4(0.f, 0.f, 0.f, 0.f);
#pragma unroll 1
    for (int c = 0; c < nch; c++) {
        const float* po = g_po + (pb + c) * 16384 + (size_t)r * 128 + cq + c8;
        float4 v0 = *reinterpret_cast<const float4*>(po);
        float4 v1 = *reinterpret_cast<const float4*>(po + 4);
        float w = wts[c];
        a0.x += w * v0.x; a0.y += w * v0.y; a0.z += w * v0.z; a0.w += w * v0.w;
        a1.x += w * v1.x; a1.y += w * v1.y; a1.z += w * v1.z; a1.w += w * v1.w;
    }
    a0.x *= inv; a0.y *= inv; a0.z *= inv; a0.w *= inv;
    a1.x *= inv; a1.y *= inv; a1.z *= inv; a1.w *= inv;

    float* orow = out + ((size_t)b * T_DIM + m * 128 + r) * H_DIM + cq + c8;
    *reinterpret_cast<float4*>(orow)     = a0;
    *reinterpret_cast<float4*>(orow + 4) = a1;
}

extern "C" void kernel_launch(void* const* d_in, const int* in_sizes, int n_in,
                              void* d_out, int out_size)
{
    const float* idx = (const float*)d_in[0];
    const float* Wq  = (const float*)d_in[1];
    const float* Wk  = (const float*)d_in[2];
    const float* Wv  = (const float*)d_in[3];
    float* out = (float*)d_out;
    (void)in_sizes; (void)n_in; (void)out_size;

    cudaFuncSetAttribute(proj_kernel, cudaFuncAttributeMaxDynamicSharedMemorySize, PJ_BYTES);
    cudaFuncSetAttribute(attn_kernel, cudaFuncAttributeMaxDynamicSharedMemorySize, ATT_BYTES);

    cvtw_kernel<<<768, 256>>>(Wq, Wk, Wv);
    proj_kernel<<<dim3(3, (B_DIM * T_DIM) / 64), 128, PJ_BYTES>>>(idx);
    attn_kernel<<<dim3(8, 32, B_DIM), 256, ATT_BYTES>>>();
    merge_kernel<<<dim3(256, B_DIM), 256>>>(out);
}